// round 1
// baseline (speedup 1.0000x reference)
#include <cuda_runtime.h>
#include <math.h>

#define MAXN 100000
#define DHID 256

// Scratch (allocation-free rule: __device__ globals)
__device__ float g_bufA[MAXN * DHID];
__device__ float g_bufB[MAXN * DHID];
__device__ float g_deg [MAXN];
__device__ float g_dinv[MAXN];

// ---------------- degree / normalization ----------------

__global__ void k_init_deg(float* deg, int N) {
    int i = blockIdx.x * blockDim.x + threadIdx.x;
    if (i < N) deg[i] = 1.0f;  // self-loop contributes 1 to every degree
}

__global__ void k_count_deg(const int* __restrict__ col, float* deg, int E) {
    int i = blockIdx.x * blockDim.x + threadIdx.x;
    if (i < E) atomicAdd(&deg[col[i]], 1.0f);
}

__global__ void k_dinv(const float* __restrict__ deg, float* dinv, int N) {
    int i = blockIdx.x * blockDim.x + threadIdx.x;
    if (i < N) {
        float d = deg[i];
        dinv[i] = d > 0.0f ? rsqrtf(d) : 0.0f;
    }
}

// ---------------- GEMM: C[M,Nc] = op(A)[M,K] @ W[K,Nc] ----------------
// 128x128 block tile, BK=16, 256 threads, 8x8 per thread, float4 I/O.
// RELU applies relu to A elements on load (fuses previous layer's activation).

template<bool RELU>
__global__ __launch_bounds__(256) void k_gemm(const float* __restrict__ A,
                                              const float* __restrict__ W,
                                              float* __restrict__ C,
                                              int M, int K, int Nc)
{
    const int BM = 128, BN = 128, BK = 16;
    __shared__ float As[BK][BM];   // transposed A tile
    __shared__ float Bs[BK][BN];

    int tid = threadIdx.x;
    int tx = tid % 16, ty = tid / 16;
    int m0 = blockIdx.x * BM;
    int n0 = blockIdx.y * BN;

    float acc[8][8] = {};

    for (int k0 = 0; k0 < K; k0 += BK) {
        // A tile: 128 rows x 16 cols = 512 float4 loads, 2 per thread
        #pragma unroll
        for (int i = 0; i < 2; i++) {
            int idx = tid + i * 256;          // 0..511
            int r   = idx >> 2;               // row in tile 0..127
            int c4  = (idx & 3) * 4;          // col 0,4,8,12
            float4 v = make_float4(0.f, 0.f, 0.f, 0.f);
            int gm = m0 + r;
            if (gm < M)
                v = *reinterpret_cast<const float4*>(&A[(size_t)gm * K + k0 + c4]);
            if (RELU) {
                v.x = fmaxf(v.x, 0.f); v.y = fmaxf(v.y, 0.f);
                v.z = fmaxf(v.z, 0.f); v.w = fmaxf(v.w, 0.f);
            }
            As[c4 + 0][r] = v.x; As[c4 + 1][r] = v.y;
            As[c4 + 2][r] = v.z; As[c4 + 3][r] = v.w;
        }
        // W tile: 16 rows x 128 cols = 512 float4 loads, 2 per thread
        #pragma unroll
        for (int i = 0; i < 2; i++) {
            int idx = tid + i * 256;
            int r   = idx >> 5;               // 0..15
            int c4  = (idx & 31) * 4;         // 0..124
            float4 v = *reinterpret_cast<const float4*>(&W[(size_t)(k0 + r) * Nc + n0 + c4]);
            *reinterpret_cast<float4*>(&Bs[r][c4]) = v;
        }
        __syncthreads();

        #pragma unroll
        for (int kk = 0; kk < BK; kk++) {
            float a[8], b[8];
            #pragma unroll
            for (int j = 0; j < 8; j++) a[j] = As[kk][ty * 8 + j];
            #pragma unroll
            for (int j = 0; j < 8; j++) b[j] = Bs[kk][tx * 8 + j];
            #pragma unroll
            for (int i2 = 0; i2 < 8; i2++)
                #pragma unroll
                for (int j = 0; j < 8; j++)
                    acc[i2][j] = fmaf(a[i2], b[j], acc[i2][j]);
        }
        __syncthreads();
    }

    #pragma unroll
    for (int i2 = 0; i2 < 8; i2++) {
        int gm = m0 + ty * 8 + i2;
        if (gm < M) {
            float4 v0 = make_float4(acc[i2][0], acc[i2][1], acc[i2][2], acc[i2][3]);
            float4 v1 = make_float4(acc[i2][4], acc[i2][5], acc[i2][6], acc[i2][7]);
            *reinterpret_cast<float4*>(&C[(size_t)gm * Nc + n0 + tx * 8])     = v0;
            *reinterpret_cast<float4*>(&C[(size_t)gm * Nc + n0 + tx * 8 + 4]) = v1;
        }
    }
}

// ---------------- aggregation ----------------
// out[n,:] = dinv[n]^2 * hw[n,:] + b   (self-loop + bias), then
// out[col[e],:] += dinv[row[e]]*dinv[col[e]] * hw[row[e],:]  for every edge.

template<int D>
__global__ void k_agg_init(const float* __restrict__ hw,
                           const float* __restrict__ b,
                           const float* __restrict__ dinv,
                           float* __restrict__ out, int N)
{
    int idx = blockIdx.x * blockDim.x + threadIdx.x;
    int total = N * (D / 4);
    if (idx >= total) return;
    int n = idx / (D / 4);
    int f = (idx % (D / 4)) * 4;
    float di = dinv[n];
    float w  = di * di;
    float4 v  = *reinterpret_cast<const float4*>(&hw[(size_t)n * D + f]);
    float4 bb = *reinterpret_cast<const float4*>(&b[f]);
    v.x = fmaf(v.x, w, bb.x);
    v.y = fmaf(v.y, w, bb.y);
    v.z = fmaf(v.z, w, bb.z);
    v.w = fmaf(v.w, w, bb.w);
    *reinterpret_cast<float4*>(&out[(size_t)n * D + f]) = v;
}

__device__ __forceinline__ void red_add_v4(float* a, float4 v) {
    asm volatile("red.global.add.v4.f32 [%0], {%1, %2, %3, %4};"
                 :: "l"(a), "f"(v.x), "f"(v.y), "f"(v.z), "f"(v.w) : "memory");
}

// One warp per edge; lane l handles float4 chunks l, l+32.
template<int D>
__global__ __launch_bounds__(256) void k_agg_edges(const float* __restrict__ hw,
                                                   float* __restrict__ out,
                                                   const int* __restrict__ row,
                                                   const int* __restrict__ col,
                                                   const float* __restrict__ dinv,
                                                   int E)
{
    int gw   = (blockIdx.x * blockDim.x + threadIdx.x) >> 5;
    int lane = threadIdx.x & 31;
    if (gw >= E) return;
    int r = __ldg(&row[gw]);
    int c = __ldg(&col[gw]);
    float coef = __ldg(&dinv[r]) * __ldg(&dinv[c]);
    const float* src = hw + (size_t)r * D;
    float*       dst = out + (size_t)c * D;
    #pragma unroll
    for (int ch = 0; ch < D / 128; ch++) {
        int f = (lane + ch * 32) * 4;
        float4 v = *reinterpret_cast<const float4*>(&src[f]);
        v.x *= coef; v.y *= coef; v.z *= coef; v.w *= coef;
        red_add_v4(&dst[f], v);
    }
}

// ---------------- launch ----------------

extern "C" void kernel_launch(void* const* d_in, const int* in_sizes, int n_in,
                              void* d_out, int out_size)
{
    const float* x  = (const float*)d_in[0];
    const int*   ei = (const int*)  d_in[1];
    const float* W0 = (const float*)d_in[4];
    const float* b0 = (const float*)d_in[5];
    const float* W1 = (const float*)d_in[6];
    const float* b1 = (const float*)d_in[7];
    const float* W2 = (const float*)d_in[8];
    const float* b2 = (const float*)d_in[9];

    int N = in_sizes[0] / 128;
    int E = in_sizes[1] / 2;
    const int* rowp = ei;
    const int* colp = ei + E;

    float *bufA, *bufB, *deg, *dinv;
    cudaGetSymbolAddress((void**)&bufA, g_bufA);
    cudaGetSymbolAddress((void**)&bufB, g_bufB);
    cudaGetSymbolAddress((void**)&deg,  g_deg);
    cudaGetSymbolAddress((void**)&dinv, g_dinv);

    float* outp = (float*)d_out;

    // normalization
    k_init_deg <<<(N + 255) / 256, 256>>>(deg, N);
    k_count_deg<<<(E + 255) / 256, 256>>>(colp, deg, E);
    k_dinv     <<<(N + 255) / 256, 256>>>(deg, dinv, N);

    dim3 gemm_block(256);
    dim3 gA((N + 127) / 128, 2);   // Nc = 256
    dim3 gC((N + 127) / 128, 1);   // Nc = 128
    int t256 = N * (256 / 4);
    int t128 = N * (128 / 4);
    int edgeBlocks = (E * 32 + 255) / 256;

    // Layer 0: x @ W0 -> bufA ; agg -> bufB (+b0); relu fused into next gemm
    k_gemm<false><<<gA, gemm_block>>>(x, W0, bufA, N, 128, 256);
    k_agg_init<256><<<(t256 + 255) / 256, 256>>>(bufA, b0, dinv, bufB, N);
    k_agg_edges<256><<<edgeBlocks, 256>>>(bufA, bufB, rowp, colp, dinv, E);

    // Layer 1: relu(bufB) @ W1 -> bufA ; agg -> bufB (+b1)
    k_gemm<true><<<gA, gemm_block>>>(bufB, W1, bufA, N, 256, 256);
    k_agg_init<256><<<(t256 + 255) / 256, 256>>>(bufA, b1, dinv, bufB, N);
    k_agg_edges<256><<<edgeBlocks, 256>>>(bufA, bufB, rowp, colp, dinv, E);

    // Layer 2: relu(bufB) @ W2 -> bufA ; agg -> d_out (+b2), no relu
    k_gemm<true><<<gC, gemm_block>>>(bufB, W2, bufA, N, 256, 128);
    k_agg_init<128><<<(t128 + 255) / 256, 256>>>(bufA, b2, dinv, outp, N);
    k_agg_edges<128><<<edgeBlocks, 256>>>(bufA, outp, rowp, colp, dinv, E);
}

// round 2
// speedup vs baseline: 1.3398x; 1.3398x over previous
#include <cuda_runtime.h>
#include <math.h>

#define MAXN 100000
#define DHID 256

// Scratch (allocation-free rule: __device__ globals)
__device__ float g_bufA[MAXN * DHID];
__device__ float g_bufB[MAXN * DHID];
__device__ float g_deg [MAXN];
__device__ float g_dinv[MAXN];

// ---------------- degree / normalization ----------------

__global__ void k_init_deg(float* deg, int N) {
    int i = blockIdx.x * blockDim.x + threadIdx.x;
    if (i < N) deg[i] = 1.0f;  // self-loop contributes 1 to every degree
}

__global__ void k_count_deg(const int* __restrict__ col, float* deg, int E) {
    int i = blockIdx.x * blockDim.x + threadIdx.x;
    if (i < E) atomicAdd(&deg[col[i]], 1.0f);
}

__global__ void k_dinv(const float* __restrict__ deg, float* dinv, int N) {
    int i = blockIdx.x * blockDim.x + threadIdx.x;
    if (i < N) {
        float d = deg[i];
        dinv[i] = d > 0.0f ? rsqrtf(d) : 0.0f;
    }
}

// ---------------- GEMM: C[M,Nc] = op(A)[M,K] @ W[K,Nc] ----------------
// 128x128 block tile, BK=16, 256 threads, 8x8 per thread, float4 I/O.
// RELU applies relu to A elements on load (fuses previous layer's activation).

template<bool RELU>
__global__ __launch_bounds__(256) void k_gemm(const float* __restrict__ A,
                                              const float* __restrict__ W,
                                              float* __restrict__ C,
                                              int M, int K, int Nc)
{
    const int BM = 128, BN = 128, BK = 16;
    __shared__ float As[BK][BM];   // transposed A tile
    __shared__ float Bs[BK][BN];

    int tid = threadIdx.x;
    int tx = tid % 16, ty = tid / 16;
    int m0 = blockIdx.x * BM;
    int n0 = blockIdx.y * BN;

    float acc[8][8] = {};

    for (int k0 = 0; k0 < K; k0 += BK) {
        // A tile: 128 rows x 16 cols = 512 float4 loads, 2 per thread
        #pragma unroll
        for (int i = 0; i < 2; i++) {
            int idx = tid + i * 256;          // 0..511
            int r   = idx >> 2;               // row in tile 0..127
            int c4  = (idx & 3) * 4;          // col 0,4,8,12
            float4 v = make_float4(0.f, 0.f, 0.f, 0.f);
            int gm = m0 + r;
            if (gm < M)
                v = *reinterpret_cast<const float4*>(&A[(size_t)gm * K + k0 + c4]);
            if (RELU) {
                v.x = fmaxf(v.x, 0.f); v.y = fmaxf(v.y, 0.f);
                v.z = fmaxf(v.z, 0.f); v.w = fmaxf(v.w, 0.f);
            }
            As[c4 + 0][r] = v.x; As[c4 + 1][r] = v.y;
            As[c4 + 2][r] = v.z; As[c4 + 3][r] = v.w;
        }
        // W tile: 16 rows x 128 cols = 512 float4 loads, 2 per thread
        #pragma unroll
        for (int i = 0; i < 2; i++) {
            int idx = tid + i * 256;
            int r   = idx >> 5;               // 0..15
            int c4  = (idx & 31) * 4;         // 0..124
            float4 v = *reinterpret_cast<const float4*>(&W[(size_t)(k0 + r) * Nc + n0 + c4]);
            *reinterpret_cast<float4*>(&Bs[r][c4]) = v;
        }
        __syncthreads();

        #pragma unroll
        for (int kk = 0; kk < BK; kk++) {
            float a[8], b[8];
            #pragma unroll
            for (int j = 0; j < 8; j++) a[j] = As[kk][ty * 8 + j];
            #pragma unroll
            for (int j = 0; j < 8; j++) b[j] = Bs[kk][tx * 8 + j];
            #pragma unroll
            for (int i2 = 0; i2 < 8; i2++)
                #pragma unroll
                for (int j = 0; j < 8; j++)
                    acc[i2][j] = fmaf(a[i2], b[j], acc[i2][j]);
        }
        __syncthreads();
    }

    #pragma unroll
    for (int i2 = 0; i2 < 8; i2++) {
        int gm = m0 + ty * 8 + i2;
        if (gm < M) {
            float4 v0 = make_float4(acc[i2][0], acc[i2][1], acc[i2][2], acc[i2][3]);
            float4 v1 = make_float4(acc[i2][4], acc[i2][5], acc[i2][6], acc[i2][7]);
            *reinterpret_cast<float4*>(&C[(size_t)gm * Nc + n0 + tx * 8])     = v0;
            *reinterpret_cast<float4*>(&C[(size_t)gm * Nc + n0 + tx * 8 + 4]) = v1;
        }
    }
}

// ---------------- aggregation ----------------
// out[n,:] = dinv[n]^2 * hw[n,:] + b   (self-loop + bias), then
// out[col[e],:] += dinv[row[e]]*dinv[col[e]] * hw[row[e],:]  for every edge.

template<int D>
__global__ void k_agg_init(const float* __restrict__ hw,
                           const float* __restrict__ b,
                           const float* __restrict__ dinv,
                           float* __restrict__ out, int N)
{
    int idx = blockIdx.x * blockDim.x + threadIdx.x;
    int total = N * (D / 4);
    if (idx >= total) return;
    int n = idx / (D / 4);
    int f = (idx % (D / 4)) * 4;
    float di = dinv[n];
    float w  = di * di;
    float4 v  = *reinterpret_cast<const float4*>(&hw[(size_t)n * D + f]);
    float4 bb = *reinterpret_cast<const float4*>(&b[f]);
    v.x = fmaf(v.x, w, bb.x);
    v.y = fmaf(v.y, w, bb.y);
    v.z = fmaf(v.z, w, bb.z);
    v.w = fmaf(v.w, w, bb.w);
    *reinterpret_cast<float4*>(&out[(size_t)n * D + f]) = v;
}

__device__ __forceinline__ void red_add_v4(float* a, float4 v) {
    asm volatile("red.global.add.v4.f32 [%0], {%1, %2, %3, %4};"
                 :: "l"(a), "f"(v.x), "f"(v.y), "f"(v.z), "f"(v.w) : "memory");
}

// One warp per edge; lane l handles float4 chunks l, l+32.
template<int D>
__global__ __launch_bounds__(256) void k_agg_edges(const float* __restrict__ hw,
                                                   float* __restrict__ out,
                                                   const int* __restrict__ row,
                                                   const int* __restrict__ col,
                                                   const float* __restrict__ dinv,
                                                   int E)
{
    int gw   = (blockIdx.x * blockDim.x + threadIdx.x) >> 5;
    int lane = threadIdx.x & 31;
    if (gw >= E) return;
    int r = __ldg(&row[gw]);
    int c = __ldg(&col[gw]);
    float coef = __ldg(&dinv[r]) * __ldg(&dinv[c]);
    const float* src = hw + (size_t)r * D;
    float*       dst = out + (size_t)c * D;
    #pragma unroll
    for (int ch = 0; ch < D / 128; ch++) {
        int f = (lane + ch * 32) * 4;
        float4 v = *reinterpret_cast<const float4*>(&src[f]);
        v.x *= coef; v.y *= coef; v.z *= coef; v.w *= coef;
        red_add_v4(&dst[f], v);
    }
}

// ---------------- launch ----------------

extern "C" void kernel_launch(void* const* d_in, const int* in_sizes, int n_in,
                              void* d_out, int out_size)
{
    const float* x  = (const float*)d_in[0];
    const int*   ei = (const int*)  d_in[1];
    const float* W0 = (const float*)d_in[4];
    const float* b0 = (const float*)d_in[5];
    const float* W1 = (const float*)d_in[6];
    const float* b1 = (const float*)d_in[7];
    const float* W2 = (const float*)d_in[8];
    const float* b2 = (const float*)d_in[9];

    int N = in_sizes[0] / 128;
    int E = in_sizes[1] / 2;
    const int* rowp = ei;
    const int* colp = ei + E;

    float *bufA, *bufB, *deg, *dinv;
    cudaGetSymbolAddress((void**)&bufA, g_bufA);
    cudaGetSymbolAddress((void**)&bufB, g_bufB);
    cudaGetSymbolAddress((void**)&deg,  g_deg);
    cudaGetSymbolAddress((void**)&dinv, g_dinv);

    float* outp = (float*)d_out;

    // normalization
    k_init_deg <<<(N + 255) / 256, 256>>>(deg, N);
    k_count_deg<<<(E + 255) / 256, 256>>>(colp, deg, E);
    k_dinv     <<<(N + 255) / 256, 256>>>(deg, dinv, N);

    dim3 gemm_block(256);
    dim3 gA((N + 127) / 128, 2);   // Nc = 256
    dim3 gC((N + 127) / 128, 1);   // Nc = 128
    int t256 = N * (256 / 4);
    int t128 = N * (128 / 4);
    int edgeBlocks = (E * 32 + 255) / 256;

    // Layer 0: x @ W0 -> bufA ; agg -> bufB (+b0); relu fused into next gemm
    k_gemm<false><<<gA, gemm_block>>>(x, W0, bufA, N, 128, 256);
    k_agg_init<256><<<(t256 + 255) / 256, 256>>>(bufA, b0, dinv, bufB, N);
    k_agg_edges<256><<<edgeBlocks, 256>>>(bufA, bufB, rowp, colp, dinv, E);

    // Layer 1: relu(bufB) @ W1 -> bufA ; agg -> bufB (+b1)
    k_gemm<true><<<gA, gemm_block>>>(bufB, W1, bufA, N, 256, 256);
    k_agg_init<256><<<(t256 + 255) / 256, 256>>>(bufA, b1, dinv, bufB, N);
    k_agg_edges<256><<<edgeBlocks, 256>>>(bufA, bufB, rowp, colp, dinv, E);

    // Layer 2: relu(bufB) @ W2 -> bufA ; agg -> d_out (+b2), no relu
    k_gemm<true><<<gC, gemm_block>>>(bufB, W2, bufA, N, 256, 128);
    k_agg_init<128><<<(t128 + 255) / 256, 256>>>(bufA, b2, dinv, outp, N);
    k_agg_edges<128><<<edgeBlocks, 256>>>(bufA, outp, rowp, colp, dinv, E);
}

// round 3
// speedup vs baseline: 2.2360x; 1.6689x over previous
#include <cuda_runtime.h>
#include <math.h>

#define MAXN 100000
#define MAXE 1600000
#define DHID 256
#define SCAN_ITEMS 2048   // 256 threads x 8 items

// Scratch (allocation-free rule: __device__ globals)
__device__ float g_bufA[MAXN * DHID];
__device__ float g_bufB[MAXN * DHID];
__device__ float g_dinv[MAXN];
__device__ int   g_cnt   [MAXN];
__device__ int   g_rowptr[MAXN + 1];
__device__ int   g_cursor[MAXN];
__device__ int   g_blockSums[64];
__device__ int   g_blockOff [64];
__device__ int2  g_edges[MAXE];

// ---------------- CSR build (group edges by destination col) ----------------

__global__ void k_zero_cnt(int* cnt, int N) {
    int i = blockIdx.x * blockDim.x + threadIdx.x;
    if (i < N) cnt[i] = 0;
}

__global__ void k_hist(const int* __restrict__ col, int* cnt, int E) {
    int i = blockIdx.x * blockDim.x + threadIdx.x;
    if (i < E) atomicAdd(&cnt[col[i]], 1);
}

__global__ void k_dinv(const int* __restrict__ cnt, float* dinv, int N) {
    int i = blockIdx.x * blockDim.x + threadIdx.x;
    if (i < N) dinv[i] = rsqrtf((float)(cnt[i] + 1));   // +1 self-loop
}

// Block-level exclusive scan: each block covers SCAN_ITEMS entries.
__global__ __launch_bounds__(256) void k_scan1(const int* __restrict__ cnt,
                                               int* rowptr, int* blockSums, int N)
{
    __shared__ int sh[256];
    int base = blockIdx.x * SCAN_ITEMS;
    int vals[8];
    int sum = 0;
    #pragma unroll
    for (int j = 0; j < 8; j++) {
        int idx = base + threadIdx.x * 8 + j;
        int v = (idx < N) ? cnt[idx] : 0;
        vals[j] = sum;           // exclusive within thread
        sum += v;
    }
    sh[threadIdx.x] = sum;
    __syncthreads();
    // inclusive Hillis-Steele over 256 thread sums
    #pragma unroll
    for (int off = 1; off < 256; off <<= 1) {
        int t = (threadIdx.x >= off) ? sh[threadIdx.x - off] : 0;
        __syncthreads();
        sh[threadIdx.x] += t;
        __syncthreads();
    }
    int thOff = (threadIdx.x > 0) ? sh[threadIdx.x - 1] : 0;
    #pragma unroll
    for (int j = 0; j < 8; j++) {
        int idx = base + threadIdx.x * 8 + j;
        if (idx < N) rowptr[idx] = thOff + vals[j];
    }
    if (threadIdx.x == 255) blockSums[blockIdx.x] = sh[255];
}

__global__ void k_scan2(const int* __restrict__ blockSums, int* blockOff, int nb) {
    __shared__ int sh[64];
    int tid = threadIdx.x;
    sh[tid] = (tid < nb) ? blockSums[tid] : 0;
    __syncthreads();
    #pragma unroll
    for (int off = 1; off < 64; off <<= 1) {
        int t = (tid >= off) ? sh[tid - off] : 0;
        __syncthreads();
        sh[tid] += t;
        __syncthreads();
    }
    if (tid < nb) blockOff[tid] = (tid > 0) ? sh[tid - 1] : 0;
}

__global__ void k_scan3(int* rowptr, int* cursor, const int* __restrict__ blockOff,
                        int N, int E)
{
    int i = blockIdx.x * blockDim.x + threadIdx.x;
    if (i < N) {
        int v = rowptr[i] + blockOff[i / SCAN_ITEMS];
        rowptr[i] = v;
        cursor[i] = v;
    }
    if (i == 0) rowptr[N] = E;
}

__global__ void k_scatter(const int* __restrict__ row, const int* __restrict__ col,
                          const float* __restrict__ dinv, int* cursor,
                          int2* edges, int E)
{
    int i = blockIdx.x * blockDim.x + threadIdx.x;
    if (i >= E) return;
    int r = row[i], c = col[i];
    int p = atomicAdd(&cursor[c], 1);
    float coef = dinv[r] * dinv[c];
    edges[p] = make_int2(r, __float_as_int(coef));
}

// ---------------- GEMM: C[M,Nc] = op(A)[M,K] @ W[K,Nc] ----------------

template<bool RELU>
__global__ __launch_bounds__(256) void k_gemm(const float* __restrict__ A,
                                              const float* __restrict__ W,
                                              float* __restrict__ C,
                                              int M, int K, int Nc)
{
    const int BM = 128, BN = 128, BK = 16;
    __shared__ float As[BK][BM];
    __shared__ float Bs[BK][BN];

    int tid = threadIdx.x;
    int tx = tid % 16, ty = tid / 16;
    int m0 = blockIdx.x * BM;
    int n0 = blockIdx.y * BN;

    float acc[8][8] = {};

    for (int k0 = 0; k0 < K; k0 += BK) {
        #pragma unroll
        for (int i = 0; i < 2; i++) {
            int idx = tid + i * 256;
            int r   = idx >> 2;
            int c4  = (idx & 3) * 4;
            float4 v = make_float4(0.f, 0.f, 0.f, 0.f);
            int gm = m0 + r;
            if (gm < M)
                v = *reinterpret_cast<const float4*>(&A[(size_t)gm * K + k0 + c4]);
            if (RELU) {
                v.x = fmaxf(v.x, 0.f); v.y = fmaxf(v.y, 0.f);
                v.z = fmaxf(v.z, 0.f); v.w = fmaxf(v.w, 0.f);
            }
            As[c4 + 0][r] = v.x; As[c4 + 1][r] = v.y;
            As[c4 + 2][r] = v.z; As[c4 + 3][r] = v.w;
        }
        #pragma unroll
        for (int i = 0; i < 2; i++) {
            int idx = tid + i * 256;
            int r   = idx >> 5;
            int c4  = (idx & 31) * 4;
            float4 v = *reinterpret_cast<const float4*>(&W[(size_t)(k0 + r) * Nc + n0 + c4]);
            *reinterpret_cast<float4*>(&Bs[r][c4]) = v;
        }
        __syncthreads();

        #pragma unroll
        for (int kk = 0; kk < BK; kk++) {
            float a[8], b[8];
            #pragma unroll
            for (int j = 0; j < 8; j++) a[j] = As[kk][ty * 8 + j];
            #pragma unroll
            for (int j = 0; j < 8; j++) b[j] = Bs[kk][tx * 8 + j];
            #pragma unroll
            for (int i2 = 0; i2 < 8; i2++)
                #pragma unroll
                for (int j = 0; j < 8; j++)
                    acc[i2][j] = fmaf(a[i2], b[j], acc[i2][j]);
        }
        __syncthreads();
    }

    #pragma unroll
    for (int i2 = 0; i2 < 8; i2++) {
        int gm = m0 + ty * 8 + i2;
        if (gm < M) {
            float4 v0 = make_float4(acc[i2][0], acc[i2][1], acc[i2][2], acc[i2][3]);
            float4 v1 = make_float4(acc[i2][4], acc[i2][5], acc[i2][6], acc[i2][7]);
            *reinterpret_cast<float4*>(&C[(size_t)gm * Nc + n0 + tx * 8])     = v0;
            *reinterpret_cast<float4*>(&C[(size_t)gm * Nc + n0 + tx * 8 + 4]) = v1;
        }
    }
}

// ---------------- aggregation: CSR gather, one warp per destination ----------------
// out[n,:] = b + dinv[n]^2 * hw[n,:] + sum_e coef[e] * hw[src[e],:]

template<int D>
__global__ __launch_bounds__(256) void k_gather(const float* __restrict__ hw,
                                                const float* __restrict__ bias,
                                                const float* __restrict__ dinv,
                                                const int* __restrict__ rowptr,
                                                const int2* __restrict__ edges,
                                                float* __restrict__ out, int N)
{
    constexpr int C = D / 128;   // float4 chunks per lane
    int n    = (blockIdx.x * blockDim.x + threadIdx.x) >> 5;
    int lane = threadIdx.x & 31;
    if (n >= N) return;

    float di = dinv[n];
    float w  = di * di;

    float4 acc[C];
    #pragma unroll
    for (int c = 0; c < C; c++) {
        int f = (lane + 32 * c) * 4;
        float4 v  = *reinterpret_cast<const float4*>(&hw[(size_t)n * D + f]);
        float4 bb = *reinterpret_cast<const float4*>(&bias[f]);
        acc[c].x = fmaf(v.x, w, bb.x);
        acc[c].y = fmaf(v.y, w, bb.y);
        acc[c].z = fmaf(v.z, w, bb.z);
        acc[c].w = fmaf(v.w, w, bb.w);
    }

    int e   = rowptr[n];
    int end = rowptr[n + 1];

    // 2x unrolled over edges for MLP
    for (; e + 1 < end; e += 2) {
        int2 e0 = __ldg(&edges[e]);
        int2 e1 = __ldg(&edges[e + 1]);
        float c0 = __int_as_float(e0.y);
        float c1 = __int_as_float(e1.y);
        const float* s0 = hw + (size_t)e0.x * D;
        const float* s1 = hw + (size_t)e1.x * D;
        #pragma unroll
        for (int c = 0; c < C; c++) {
            int f = (lane + 32 * c) * 4;
            float4 v0 = *reinterpret_cast<const float4*>(&s0[f]);
            float4 v1 = *reinterpret_cast<const float4*>(&s1[f]);
            acc[c].x = fmaf(v0.x, c0, acc[c].x); acc[c].y = fmaf(v0.y, c0, acc[c].y);
            acc[c].z = fmaf(v0.z, c0, acc[c].z); acc[c].w = fmaf(v0.w, c0, acc[c].w);
            acc[c].x = fmaf(v1.x, c1, acc[c].x); acc[c].y = fmaf(v1.y, c1, acc[c].y);
            acc[c].z = fmaf(v1.z, c1, acc[c].z); acc[c].w = fmaf(v1.w, c1, acc[c].w);
        }
    }
    if (e < end) {
        int2 e0 = __ldg(&edges[e]);
        float c0 = __int_as_float(e0.y);
        const float* s0 = hw + (size_t)e0.x * D;
        #pragma unroll
        for (int c = 0; c < C; c++) {
            int f = (lane + 32 * c) * 4;
            float4 v0 = *reinterpret_cast<const float4*>(&s0[f]);
            acc[c].x = fmaf(v0.x, c0, acc[c].x); acc[c].y = fmaf(v0.y, c0, acc[c].y);
            acc[c].z = fmaf(v0.z, c0, acc[c].z); acc[c].w = fmaf(v0.w, c0, acc[c].w);
        }
    }

    #pragma unroll
    for (int c = 0; c < C; c++) {
        int f = (lane + 32 * c) * 4;
        *reinterpret_cast<float4*>(&out[(size_t)n * D + f]) = acc[c];
    }
}

// ---------------- launch ----------------

extern "C" void kernel_launch(void* const* d_in, const int* in_sizes, int n_in,
                              void* d_out, int out_size)
{
    const float* x  = (const float*)d_in[0];
    const int*   ei = (const int*)  d_in[1];
    const float* W0 = (const float*)d_in[4];
    const float* b0 = (const float*)d_in[5];
    const float* W1 = (const float*)d_in[6];
    const float* b1 = (const float*)d_in[7];
    const float* W2 = (const float*)d_in[8];
    const float* b2 = (const float*)d_in[9];

    int N = in_sizes[0] / 128;
    int E = in_sizes[1] / 2;
    const int* rowp = ei;
    const int* colp = ei + E;

    float *bufA, *bufB, *dinv;
    int *cnt, *rowptr, *cursor, *blockSums, *blockOff;
    int2 *edges;
    cudaGetSymbolAddress((void**)&bufA,      g_bufA);
    cudaGetSymbolAddress((void**)&bufB,      g_bufB);
    cudaGetSymbolAddress((void**)&dinv,      g_dinv);
    cudaGetSymbolAddress((void**)&cnt,       g_cnt);
    cudaGetSymbolAddress((void**)&rowptr,    g_rowptr);
    cudaGetSymbolAddress((void**)&cursor,    g_cursor);
    cudaGetSymbolAddress((void**)&blockSums, g_blockSums);
    cudaGetSymbolAddress((void**)&blockOff,  g_blockOff);
    cudaGetSymbolAddress((void**)&edges,     g_edges);

    float* outp = (float*)d_out;

    int nb = (N + SCAN_ITEMS - 1) / SCAN_ITEMS;   // 49 for N=100K

    // CSR build
    k_zero_cnt<<<(N + 255) / 256, 256>>>(cnt, N);
    k_hist    <<<(E + 255) / 256, 256>>>(colp, cnt, E);
    k_dinv    <<<(N + 255) / 256, 256>>>(cnt, dinv, N);
    k_scan1   <<<nb, 256>>>(cnt, rowptr, blockSums, N);
    k_scan2   <<<1, 64>>>(blockSums, blockOff, nb);
    k_scan3   <<<(N + 255) / 256, 256>>>(rowptr, cursor, blockOff, N, E);
    k_scatter <<<(E + 255) / 256, 256>>>(rowp, colp, dinv, cursor, edges, E);

    dim3 gemm_block(256);
    dim3 gA((N + 127) / 128, 2);   // Nc = 256
    dim3 gC((N + 127) / 128, 1);   // Nc = 128
    int gatherBlocks = (N * 32 + 255) / 256;

    // Layer 0
    k_gemm<false><<<gA, gemm_block>>>(x, W0, bufA, N, 128, 256);
    k_gather<256><<<gatherBlocks, 256>>>(bufA, b0, dinv, rowptr, edges, bufB, N);

    // Layer 1 (relu fused into GEMM A-load)
    k_gemm<true><<<gA, gemm_block>>>(bufB, W1, bufA, N, 256, 256);
    k_gather<256><<<gatherBlocks, 256>>>(bufA, b1, dinv, rowptr, edges, bufB, N);

    // Layer 2
    k_gemm<true><<<gC, gemm_block>>>(bufB, W2, bufA, N, 256, 128);
    k_gather<128><<<gatherBlocks, 256>>>(bufA, b2, dinv, rowptr, edges, outp, N);
}

// round 5
// speedup vs baseline: 3.3115x; 1.4810x over previous
#include <cuda_runtime.h>
#include <cuda_bf16.h>
#include <math.h>
#include <stdint.h>

#define MAXN 100000
#define MAXE 1600000
#define DHID 256
#define SCAN_ITEMS 2048   // 256 threads x 8 items

// ---------------- scratch (__device__ globals; allocation-free rule) ----------------
__device__ float          g_bufF[MAXN * DHID];       // fp32 GEMM output
__device__ __nv_bfloat16  g_hsHi[MAXN * DHID];       // bf16 split of GEMM input
__device__ __nv_bfloat16  g_hsLo[MAXN * DHID];
__device__ __nv_bfloat16  g_wtHi[3][65536];          // transposed weights, split
__device__ __nv_bfloat16  g_wtLo[3][65536];
__device__ float g_dinv[MAXN];
__device__ int   g_cnt   [MAXN];
__device__ int   g_rowptr[MAXN + 1];
__device__ int   g_cursor[MAXN];
__device__ int   g_blockSums[64];
__device__ int   g_blockOff [64];
__device__ int2  g_edges[MAXE];

// ---------------- CSR build ----------------

__global__ void k_zero_cnt(int* cnt, int N) {
    int i = blockIdx.x * blockDim.x + threadIdx.x;
    if (i < N) cnt[i] = 0;
}
__global__ void k_hist(const int* __restrict__ col, int* cnt, int E) {
    int i = blockIdx.x * blockDim.x + threadIdx.x;
    if (i < E) atomicAdd(&cnt[col[i]], 1);
}
__global__ void k_dinv(const int* __restrict__ cnt, float* dinv, int N) {
    int i = blockIdx.x * blockDim.x + threadIdx.x;
    if (i < N) dinv[i] = rsqrtf((float)(cnt[i] + 1));
}
__global__ __launch_bounds__(256) void k_scan1(const int* __restrict__ cnt,
                                               int* rowptr, int* blockSums, int N) {
    __shared__ int sh[256];
    int base = blockIdx.x * SCAN_ITEMS;
    int vals[8];
    int sum = 0;
    #pragma unroll
    for (int j = 0; j < 8; j++) {
        int idx = base + threadIdx.x * 8 + j;
        int v = (idx < N) ? cnt[idx] : 0;
        vals[j] = sum;
        sum += v;
    }
    sh[threadIdx.x] = sum;
    __syncthreads();
    #pragma unroll
    for (int off = 1; off < 256; off <<= 1) {
        int t = (threadIdx.x >= off) ? sh[threadIdx.x - off] : 0;
        __syncthreads();
        sh[threadIdx.x] += t;
        __syncthreads();
    }
    int thOff = (threadIdx.x > 0) ? sh[threadIdx.x - 1] : 0;
    #pragma unroll
    for (int j = 0; j < 8; j++) {
        int idx = base + threadIdx.x * 8 + j;
        if (idx < N) rowptr[idx] = thOff + vals[j];
    }
    if (threadIdx.x == 255) blockSums[blockIdx.x] = sh[255];
}
__global__ void k_scan2(const int* __restrict__ blockSums, int* blockOff, int nb) {
    __shared__ int sh[64];
    int tid = threadIdx.x;
    sh[tid] = (tid < nb) ? blockSums[tid] : 0;
    __syncthreads();
    #pragma unroll
    for (int off = 1; off < 64; off <<= 1) {
        int t = (tid >= off) ? sh[tid - off] : 0;
        __syncthreads();
        sh[tid] += t;
        __syncthreads();
    }
    if (tid < nb) blockOff[tid] = (tid > 0) ? sh[tid - 1] : 0;
}
__global__ void k_scan3(int* rowptr, int* cursor, const int* __restrict__ blockOff,
                        int N, int E) {
    int i = blockIdx.x * blockDim.x + threadIdx.x;
    if (i < N) {
        int v = rowptr[i] + blockOff[i / SCAN_ITEMS];
        rowptr[i] = v;
        cursor[i] = v;
    }
    if (i == 0) rowptr[N] = E;
}
__global__ void k_scatter(const int* __restrict__ row, const int* __restrict__ col,
                          const float* __restrict__ dinv, int* cursor,
                          int2* edges, int E) {
    int i = blockIdx.x * blockDim.x + threadIdx.x;
    if (i >= E) return;
    int r = row[i], c = col[i];
    int p = atomicAdd(&cursor[c], 1);
    float coef = dinv[r] * dinv[c];
    edges[p] = make_int2(r, __float_as_int(coef));
}

// ---------------- fp32 -> bf16 hi/lo split helpers ----------------

__device__ __forceinline__ void split2(float a, float b,
                                       __nv_bfloat162& hi, __nv_bfloat162& lo) {
    __nv_bfloat16 ha = __float2bfloat16(a);
    __nv_bfloat16 hb = __float2bfloat16(b);
    __nv_bfloat16 la = __float2bfloat16(a - __bfloat162float(ha));
    __nv_bfloat16 lb = __float2bfloat16(b - __bfloat162float(hb));
    hi = __halves2bfloat162(ha, hb);
    lo = __halves2bfloat162(la, lb);
}

__global__ void k_split_x(const float* __restrict__ x,
                          __nv_bfloat16* __restrict__ oh,
                          __nv_bfloat16* __restrict__ ol, int total4) {
    int t = blockIdx.x * blockDim.x + threadIdx.x;
    if (t >= total4) return;
    float4 v = *reinterpret_cast<const float4*>(&x[t * 4]);
    __nv_bfloat162 h0, l0, h1, l1;
    split2(v.x, v.y, h0, l0);
    split2(v.z, v.w, h1, l1);
    *reinterpret_cast<__nv_bfloat162*>(&oh[t * 4])     = h0;
    *reinterpret_cast<__nv_bfloat162*>(&oh[t * 4 + 2]) = h1;
    *reinterpret_cast<__nv_bfloat162*>(&ol[t * 4])     = l0;
    *reinterpret_cast<__nv_bfloat162*>(&ol[t * 4 + 2]) = l1;
}

// transpose + split W [K,Nc] -> WT hi/lo [Nc,K]
__global__ void k_split_wt(const float* __restrict__ W,
                           __nv_bfloat16* __restrict__ oh,
                           __nv_bfloat16* __restrict__ ol, int K, int Nc) {
    int t = blockIdx.x * blockDim.x + threadIdx.x;
    if (t >= K * Nc) return;
    int n = t / K, k = t % K;
    float a = W[k * Nc + n];
    __nv_bfloat16 h = __float2bfloat16(a);
    __nv_bfloat16 l = __float2bfloat16(a - __bfloat162float(h));
    oh[t] = h;
    ol[t] = l;
}

// ---------------- tensor-core GEMM via mma.sync (bf16, 3-term split) ----------------
// C[M,Nc] = (Ahi+Alo)[M,K] @ (WThi+WTlo)^T, fp32 accum.
// A: [M,K] bf16 row-major.  WT: [Nc,K] bf16 row-major.  C: [M,Nc] fp32.
// CTA: 128x128 tile, BK=32, 256 threads = 8 warps (4m x 2n), warp tile 32x64.

#define GSTRIDE 40                    // smem row stride in bf16 (80 B)
#define TILE_BYTES (128 * GSTRIDE * 2)   // 10240 B per tile
#define BUF_BYTES  (4 * TILE_BYTES)      // Ahi, Alo, Bhi, Blo
#define SMEM_TOTAL_G (2 * BUF_BYTES)     // double buffer: 81920 B

__device__ __forceinline__ uint32_t smem_u32(const void* p) {
    uint32_t a;
    asm("{ .reg .u64 t; cvta.to.shared.u64 t, %1; cvt.u32.u64 %0, t; }" : "=r"(a) : "l"(p));
    return a;
}
__device__ __forceinline__ void cp16(uint32_t dst, const void* src, int srcsize) {
    asm volatile("cp.async.cg.shared.global [%0], [%1], 16, %2;"
                 :: "r"(dst), "l"(src), "r"(srcsize) : "memory");
}
__device__ __forceinline__ void cp_commit() {
    asm volatile("cp.async.commit_group;" ::: "memory");
}
template<int Ngroups>
__device__ __forceinline__ void cp_wait() {
    asm volatile("cp.async.wait_group %0;" :: "n"(Ngroups) : "memory");
}
__device__ __forceinline__ void mma16816(float* c, const uint32_t* a, const uint32_t* b) {
    asm volatile("mma.sync.aligned.m16n8k16.row.col.f32.bf16.bf16.f32 "
                 "{%0,%1,%2,%3}, {%4,%5,%6,%7}, {%8,%9}, {%0,%1,%2,%3};"
                 : "+f"(c[0]), "+f"(c[1]), "+f"(c[2]), "+f"(c[3])
                 : "r"(a[0]), "r"(a[1]), "r"(a[2]), "r"(a[3]), "r"(b[0]), "r"(b[1]));
}

__global__ __launch_bounds__(256) void k_gemm_mma(
    const __nv_bfloat16* __restrict__ Ahi, const __nv_bfloat16* __restrict__ Alo,
    const __nv_bfloat16* __restrict__ Bhi, const __nv_bfloat16* __restrict__ Blo,
    float* __restrict__ C, int M, int K, int Nc)
{
    extern __shared__ __align__(16) char smem[];
    const uint32_t sbase = smem_u32(smem);

    int tid = threadIdx.x;
    int wid = tid >> 5;
    int lane = tid & 31;
    int wm = wid & 3;          // 0..3 -> m offset 32*wm
    int wn = wid >> 2;         // 0..1 -> n offset 64*wn
    int g = lane >> 2;         // 0..7
    int q = lane & 3;          // 0..3
    int m0 = blockIdx.y * 128;
    int n0 = blockIdx.x * 128;

    float acc[2][8][4];
    #pragma unroll
    for (int mi = 0; mi < 2; mi++)
        #pragma unroll
        for (int ni = 0; ni < 8; ni++)
            #pragma unroll
            for (int r = 0; r < 4; r++) acc[mi][ni][r] = 0.f;

    int nchunks = K >> 5;

    // ---- async load of one chunk into buffer b ----
    auto load_chunk = [&](int c, int b) {
        uint32_t buf = sbase + b * BUF_BYTES;
        int kc = c * 32;
        #pragma unroll
        for (int i = 0; i < 2; i++) {
            int s   = tid + i * 256;   // 0..511
            int row = s >> 2;
            int cs  = s & 3;
            uint32_t soff = row * (GSTRIDE * 2) + cs * 16;
            // A tiles (guard M)
            int am = m0 + row;
            int ok = (am < M) ? 16 : 0;
            size_t aoff = (size_t)(ok ? am : 0) * K + kc + cs * 8;
            cp16(buf + 0 * TILE_BYTES + soff, Ahi + aoff, ok);
            cp16(buf + 1 * TILE_BYTES + soff, Alo + aoff, ok);
            // B tiles (always full: Nc multiple of 128)
            size_t boff = (size_t)(n0 + row) * K + kc + cs * 8;
            cp16(buf + 2 * TILE_BYTES + soff, Bhi + boff, 16);
            cp16(buf + 3 * TILE_BYTES + soff, Blo + boff, 16);
        }
        cp_commit();
    };

    load_chunk(0, 0);

    for (int c = 0; c < nchunks; c++) {
        if (c + 1 < nchunks) {
            load_chunk(c + 1, (c + 1) & 1);
            cp_wait<1>();
        } else {
            cp_wait<0>();
        }
        __syncthreads();

        uint32_t buf = sbase + (c & 1) * BUF_BYTES;
        uint32_t aHi = buf + 0 * TILE_BYTES;
        uint32_t aLo = buf + 1 * TILE_BYTES;
        uint32_t bHi = buf + 2 * TILE_BYTES;
        uint32_t bLo = buf + 3 * TILE_BYTES;

        #pragma unroll
        for (int ks = 0; ks < 2; ks++) {
            int kb = ks * 32;   // byte offset of k-step (16 bf16)
            uint32_t ah[2][4], al[2][4];
            #pragma unroll
            for (int mi = 0; mi < 2; mi++) {
                uint32_t a0 = aHi + (wm * 32 + mi * 16 + g) * 80 + kb + q * 4;
                ah[mi][0] = *(const uint32_t*)__cvta_shared_to_generic(a0);
                ah[mi][1] = *(const uint32_t*)__cvta_shared_to_generic(a0 + 640);
                ah[mi][2] = *(const uint32_t*)__cvta_shared_to_generic(a0 + 16);
                ah[mi][3] = *(const uint32_t*)__cvta_shared_to_generic(a0 + 656);
                uint32_t a1 = aLo + (wm * 32 + mi * 16 + g) * 80 + kb + q * 4;
                al[mi][0] = *(const uint32_t*)__cvta_shared_to_generic(a1);
                al[mi][1] = *(const uint32_t*)__cvta_shared_to_generic(a1 + 640);
                al[mi][2] = *(const uint32_t*)__cvta_shared_to_generic(a1 + 16);
                al[mi][3] = *(const uint32_t*)__cvta_shared_to_generic(a1 + 656);
            }
            #pragma unroll
            for (int ni = 0; ni < 8; ni++) {
                uint32_t bh[2], bl[2];
                uint32_t b0 = bHi + (wn * 64 + ni * 8 + g) * 80 + kb + q * 4;
                bh[0] = *(const uint32_t*)__cvta_shared_to_generic(b0);
                bh[1] = *(const uint32_t*)__cvta_shared_to_generic(b0 + 16);
                uint32_t b1 = bLo + (wn * 64 + ni * 8 + g) * 80 + kb + q * 4;
                bl[0] = *(const uint32_t*)__cvta_shared_to_generic(b1);
                bl[1] = *(const uint32_t*)__cvta_shared_to_generic(b1 + 16);
                #pragma unroll
                for (int mi = 0; mi < 2; mi++) {
                    mma16816(acc[mi][ni], ah[mi], bh);
                    mma16816(acc[mi][ni], ah[mi], bl);
                    mma16816(acc[mi][ni], al[mi], bh);
                }
            }
        }
        __syncthreads();
    }

    // ---- epilogue ----
    #pragma unroll
    for (int mi = 0; mi < 2; mi++) {
        int r0 = m0 + wm * 32 + mi * 16 + g;
        int r1 = r0 + 8;
        #pragma unroll
        for (int ni = 0; ni < 8; ni++) {
            int colg = n0 + wn * 64 + ni * 8 + q * 2;
            if (r0 < M)
                *reinterpret_cast<float2*>(&C[(size_t)r0 * Nc + colg]) =
                    make_float2(acc[mi][ni][0], acc[mi][ni][1]);
            if (r1 < M)
                *reinterpret_cast<float2*>(&C[(size_t)r1 * Nc + colg]) =
                    make_float2(acc[mi][ni][2], acc[mi][ni][3]);
        }
    }
}

// ---------------- aggregation: CSR gather, one warp per destination ----------------

template<int D, bool SPLIT>
__global__ __launch_bounds__(256) void k_gather(const float* __restrict__ hw,
                                                const float* __restrict__ bias,
                                                const float* __restrict__ dinv,
                                                const int* __restrict__ rowptr,
                                                const int2* __restrict__ edges,
                                                float* __restrict__ out,
                                                __nv_bfloat16* __restrict__ outHi,
                                                __nv_bfloat16* __restrict__ outLo,
                                                int N)
{
    constexpr int C = D / 128;
    int n    = (blockIdx.x * blockDim.x + threadIdx.x) >> 5;
    int lane = threadIdx.x & 31;
    if (n >= N) return;

    float di = dinv[n];
    float w  = di * di;

    float4 acc[C];
    #pragma unroll
    for (int c = 0; c < C; c++) {
        int f = (lane + 32 * c) * 4;
        float4 v  = *reinterpret_cast<const float4*>(&hw[(size_t)n * D + f]);
        float4 bb = *reinterpret_cast<const float4*>(&bias[f]);
        acc[c].x = fmaf(v.x, w, bb.x);
        acc[c].y = fmaf(v.y, w, bb.y);
        acc[c].z = fmaf(v.z, w, bb.z);
        acc[c].w = fmaf(v.w, w, bb.w);
    }

    int e   = rowptr[n];
    int end = rowptr[n + 1];

    for (; e + 1 < end; e += 2) {
        int2 e0 = __ldg(&edges[e]);
        int2 e1 = __ldg(&edges[e + 1]);
        float c0 = __int_as_float(e0.y);
        float c1 = __int_as_float(e1.y);
        const float* s0 = hw + (size_t)e0.x * D;
        const float* s1 = hw + (size_t)e1.x * D;
        #pragma unroll
        for (int c = 0; c < C; c++) {
            int f = (lane + 32 * c) * 4;
            float4 v0 = *reinterpret_cast<const float4*>(&s0[f]);
            float4 v1 = *reinterpret_cast<const float4*>(&s1[f]);
            acc[c].x = fmaf(v0.x, c0, acc[c].x); acc[c].y = fmaf(v0.y, c0, acc[c].y);
            acc[c].z = fmaf(v0.z, c0, acc[c].z); acc[c].w = fmaf(v0.w, c0, acc[c].w);
            acc[c].x = fmaf(v1.x, c1, acc[c].x); acc[c].y = fmaf(v1.y, c1, acc[c].y);
            acc[c].z = fmaf(v1.z, c1, acc[c].z); acc[c].w = fmaf(v1.w, c1, acc[c].w);
        }
    }
    if (e < end) {
        int2 e0 = __ldg(&edges[e]);
        float c0 = __int_as_float(e0.y);
        const float* s0 = hw + (size_t)e0.x * D;
        #pragma unroll
        for (int c = 0; c < C; c++) {
            int f = (lane + 32 * c) * 4;
            float4 v0 = *reinterpret_cast<const float4*>(&s0[f]);
            acc[c].x = fmaf(v0.x, c0, acc[c].x); acc[c].y = fmaf(v0.y, c0, acc[c].y);
            acc[c].z = fmaf(v0.z, c0, acc[c].z); acc[c].w = fmaf(v0.w, c0, acc[c].w);
        }
    }

    #pragma unroll
    for (int c = 0; c < C; c++) {
        int f = (lane + 32 * c) * 4;
        if (SPLIT) {
            float4 r = acc[c];
            r.x = fmaxf(r.x, 0.f); r.y = fmaxf(r.y, 0.f);
            r.z = fmaxf(r.z, 0.f); r.w = fmaxf(r.w, 0.f);
            __nv_bfloat162 h0, l0, h1, l1;
            split2(r.x, r.y, h0, l0);
            split2(r.z, r.w, h1, l1);
            *reinterpret_cast<__nv_bfloat162*>(&outHi[(size_t)n * D + f])     = h0;
            *reinterpret_cast<__nv_bfloat162*>(&outHi[(size_t)n * D + f + 2]) = h1;
            *reinterpret_cast<__nv_bfloat162*>(&outLo[(size_t)n * D + f])     = l0;
            *reinterpret_cast<__nv_bfloat162*>(&outLo[(size_t)n * D + f + 2]) = l1;
        } else {
            *reinterpret_cast<float4*>(&out[(size_t)n * D + f]) = acc[c];
        }
    }
}

// ---------------- launch ----------------

extern "C" void kernel_launch(void* const* d_in, const int* in_sizes, int n_in,
                              void* d_out, int out_size)
{
    const float* x  = (const float*)d_in[0];
    const int*   ei = (const int*)  d_in[1];
    const float* W0 = (const float*)d_in[4];
    const float* b0 = (const float*)d_in[5];
    const float* W1 = (const float*)d_in[6];
    const float* b1 = (const float*)d_in[7];
    const float* W2 = (const float*)d_in[8];
    const float* b2 = (const float*)d_in[9];

    int N = in_sizes[0] / 128;
    int E = in_sizes[1] / 2;
    const int* rowp = ei;
    const int* colp = ei + E;

    float *bufF, *dinv;
    __nv_bfloat16 *hsHi, *hsLo, *wtHi, *wtLo;
    int *cnt, *rowptr, *cursor, *blockSums, *blockOff;
    int2 *edges;
    cudaGetSymbolAddress((void**)&bufF,      g_bufF);
    cudaGetSymbolAddress((void**)&hsHi,      g_hsHi);
    cudaGetSymbolAddress((void**)&hsLo,      g_hsLo);
    cudaGetSymbolAddress((void**)&wtHi,      g_wtHi);
    cudaGetSymbolAddress((void**)&wtLo,      g_wtLo);
    cudaGetSymbolAddress((void**)&dinv,      g_dinv);
    cudaGetSymbolAddress((void**)&cnt,       g_cnt);
    cudaGetSymbolAddress((void**)&rowptr,    g_rowptr);
    cudaGetSymbolAddress((void**)&cursor,    g_cursor);
    cudaGetSymbolAddress((void**)&blockSums, g_blockSums);
    cudaGetSymbolAddress((void**)&blockOff,  g_blockOff);
    cudaGetSymbolAddress((void**)&edges,     g_edges);

    float* outp = (float*)d_out;

    static bool attrSet = false;
    if (!attrSet) {
        cudaFuncSetAttribute(k_gemm_mma, cudaFuncAttributeMaxDynamicSharedMemorySize,
                             SMEM_TOTAL_G);
        attrSet = true;
    }

    int nb = (N + SCAN_ITEMS - 1) / SCAN_ITEMS;

    // CSR build + norm
    k_zero_cnt<<<(N + 255) / 256, 256>>>(cnt, N);
    k_hist    <<<(E + 255) / 256, 256>>>(colp, cnt, E);
    k_dinv    <<<(N + 255) / 256, 256>>>(cnt, dinv, N);
    k_scan1   <<<nb, 256>>>(cnt, rowptr, blockSums, N);
    k_scan2   <<<1, 64>>>(blockSums, blockOff, nb);
    k_scan3   <<<(N + 255) / 256, 256>>>(rowptr, cursor, blockOff, N, E);
    k_scatter <<<(E + 255) / 256, 256>>>(rowp, colp, dinv, cursor, edges, E);

    // weight + input splits
    k_split_wt<<<(128 * 256 + 255) / 256, 256>>>(W0, wtHi + 0 * 65536, wtLo + 0 * 65536, 128, 256);
    k_split_wt<<<(256 * 256 + 255) / 256, 256>>>(W1, wtHi + 1 * 65536, wtLo + 1 * 65536, 256, 256);
    k_split_wt<<<(256 * 128 + 255) / 256, 256>>>(W2, wtHi + 2 * 65536, wtLo + 2 * 65536, 256, 128);
    k_split_x <<<(N * 32 + 255) / 256, 256>>>(x, hsHi, hsLo, N * 32);

    int mt = (N + 127) / 128;
    int gatherBlocks = (N * 32 + 255) / 256;

    // Layer 0: [N,128]@[128,256]
    k_gemm_mma<<<dim3(2, mt), 256, SMEM_TOTAL_G>>>(hsHi, hsLo, wtHi + 0 * 65536, wtLo + 0 * 65536,
                                                   bufF, N, 128, 256);
    k_gather<256, true><<<gatherBlocks, 256>>>(bufF, b0, dinv, rowptr, edges,
                                               nullptr, hsHi, hsLo, N);
    // Layer 1: [N,256]@[256,256]
    k_gemm_mma<<<dim3(2, mt), 256, SMEM_TOTAL_G>>>(hsHi, hsLo, wtHi + 1 * 65536, wtLo + 1 * 65536,
                                                   bufF, N, 256, 256);
    k_gather<256, true><<<gatherBlocks, 256>>>(bufF, b1, dinv, rowptr, edges,
                                               nullptr, hsHi, hsLo, N);
    // Layer 2: [N,256]@[256,128]
    k_gemm_mma<<<dim3(1, mt), 256, SMEM_TOTAL_G>>>(hsHi, hsLo, wtHi + 2 * 65536, wtLo + 2 * 65536,
                                                   bufF, N, 256, 128);
    k_gather<128, false><<<gatherBlocks, 256>>>(bufF, b2, dinv, rowptr, edges,
                                                outp, nullptr, nullptr, N);
}

// round 6
// speedup vs baseline: 3.6854x; 1.1129x over previous
#include <cuda_runtime.h>
#include <cuda_bf16.h>
#include <math.h>
#include <stdint.h>

#define MAXN 100000
#define MAXE 1600000
#define DHID 256
#define SCAN_ITEMS 2048   // 256 threads x 8 items

// ---------------- scratch (__device__ globals; allocation-free rule) ----------------
__device__ float          g_bufF[MAXN * DHID];       // fp32 GEMM output
__device__ __nv_bfloat16  g_bAHi[MAXN * DHID];       // bf16 split buffers (ping)
__device__ __nv_bfloat16  g_bALo[MAXN * DHID];
__device__ __nv_bfloat16  g_bBHi[MAXN * DHID];       // bf16 split buffers (pong)
__device__ __nv_bfloat16  g_bBLo[MAXN * DHID];
__device__ __nv_bfloat16  g_wtHi[3][65536];          // transposed weights, split
__device__ __nv_bfloat16  g_wtLo[3][65536];
__device__ float g_dinv[MAXN];
__device__ int   g_cnt   [MAXN];
__device__ int   g_rowptr[MAXN + 1];
__device__ int   g_cursor[MAXN];
__device__ int   g_blockSums[64];
__device__ int   g_blockOff [64];
__device__ int2  g_edges[MAXE];

// ---------------- CSR build ----------------

__global__ void k_zero_cnt(int* cnt, int N) {
    int i = blockIdx.x * blockDim.x + threadIdx.x;
    if (i < N) cnt[i] = 0;
}
__global__ void k_hist(const int* __restrict__ col, int* cnt, int E) {
    int i = blockIdx.x * blockDim.x + threadIdx.x;
    if (i < E) atomicAdd(&cnt[col[i]], 1);
}
__global__ void k_dinv(const int* __restrict__ cnt, float* dinv, int N) {
    int i = blockIdx.x * blockDim.x + threadIdx.x;
    if (i < N) dinv[i] = rsqrtf((float)(cnt[i] + 1));
}
__global__ __launch_bounds__(256) void k_scan1(const int* __restrict__ cnt,
                                               int* rowptr, int* blockSums, int N) {
    __shared__ int sh[256];
    int base = blockIdx.x * SCAN_ITEMS;
    int vals[8];
    int sum = 0;
    #pragma unroll
    for (int j = 0; j < 8; j++) {
        int idx = base + threadIdx.x * 8 + j;
        int v = (idx < N) ? cnt[idx] : 0;
        vals[j] = sum;
        sum += v;
    }
    sh[threadIdx.x] = sum;
    __syncthreads();
    #pragma unroll
    for (int off = 1; off < 256; off <<= 1) {
        int t = (threadIdx.x >= off) ? sh[threadIdx.x - off] : 0;
        __syncthreads();
        sh[threadIdx.x] += t;
        __syncthreads();
    }
    int thOff = (threadIdx.x > 0) ? sh[threadIdx.x - 1] : 0;
    #pragma unroll
    for (int j = 0; j < 8; j++) {
        int idx = base + threadIdx.x * 8 + j;
        if (idx < N) rowptr[idx] = thOff + vals[j];
    }
    if (threadIdx.x == 255) blockSums[blockIdx.x] = sh[255];
}
__global__ void k_scan2(const int* __restrict__ blockSums, int* blockOff, int nb) {
    __shared__ int sh[64];
    int tid = threadIdx.x;
    sh[tid] = (tid < nb) ? blockSums[tid] : 0;
    __syncthreads();
    #pragma unroll
    for (int off = 1; off < 64; off <<= 1) {
        int t = (tid >= off) ? sh[tid - off] : 0;
        __syncthreads();
        sh[tid] += t;
        __syncthreads();
    }
    if (tid < nb) blockOff[tid] = (tid > 0) ? sh[tid - 1] : 0;
}
__global__ void k_scan3(int* rowptr, int* cursor, const int* __restrict__ blockOff,
                        int N, int E) {
    int i = blockIdx.x * blockDim.x + threadIdx.x;
    if (i < N) {
        int v = rowptr[i] + blockOff[i / SCAN_ITEMS];
        rowptr[i] = v;
        cursor[i] = v;
    }
    if (i == 0) rowptr[N] = E;
}
__global__ void k_scatter(const int* __restrict__ row, const int* __restrict__ col,
                          const float* __restrict__ dinv, int* cursor,
                          int2* edges, int E) {
    int i = blockIdx.x * blockDim.x + threadIdx.x;
    if (i >= E) return;
    int r = row[i], c = col[i];
    int p = atomicAdd(&cursor[c], 1);
    float coef = dinv[r] * dinv[c];
    edges[p] = make_int2(r, __float_as_int(coef));
}

// ---------------- fp32 -> bf16 hi/lo split helpers ----------------

__device__ __forceinline__ void split2(float a, float b,
                                       __nv_bfloat162& hi, __nv_bfloat162& lo) {
    __nv_bfloat16 ha = __float2bfloat16(a);
    __nv_bfloat16 hb = __float2bfloat16(b);
    __nv_bfloat16 la = __float2bfloat16(a - __bfloat162float(ha));
    __nv_bfloat16 lb = __float2bfloat16(b - __bfloat162float(hb));
    hi = __halves2bfloat162(ha, hb);
    lo = __halves2bfloat162(la, lb);
}

// transpose + split W [K,Nc] -> WT hi/lo [Nc,K]
__global__ void k_split_wt(const float* __restrict__ W,
                           __nv_bfloat16* __restrict__ oh,
                           __nv_bfloat16* __restrict__ ol, int K, int Nc) {
    int t = blockIdx.x * blockDim.x + threadIdx.x;
    if (t >= K * Nc) return;
    int n = t / K, k = t % K;
    float a = W[k * Nc + n];
    __nv_bfloat16 h = __float2bfloat16(a);
    __nv_bfloat16 l = __float2bfloat16(a - __bfloat162float(h));
    oh[t] = h;
    ol[t] = l;
}

// ---------------- tensor-core GEMM via mma.sync (bf16, 3-term split) ----------------
// C[M,Nc] = (Ahi+Alo)[M,K] @ (WThi+WTlo)^T, fp32 accum.
// EPI=0: write fp32 C.  EPI=1: relu(C + bias) -> bf16 hi/lo split outputs.
// CTA: 128x128 tile, BK=32, 256 threads = 8 warps (4m x 2n), warp tile 32x64.

#define GSTRIDE 40                       // smem row stride in bf16 (80 B)
#define TILE_BYTES (128 * GSTRIDE * 2)   // 10240 B per tile
#define BUF_BYTES  (4 * TILE_BYTES)
#define SMEM_TOTAL_G (2 * BUF_BYTES)     // 81920 B

__device__ __forceinline__ uint32_t smem_u32(const void* p) {
    uint32_t a;
    asm("{ .reg .u64 t; cvta.to.shared.u64 t, %1; cvt.u32.u64 %0, t; }" : "=r"(a) : "l"(p));
    return a;
}
__device__ __forceinline__ void cp16(uint32_t dst, const void* src, int srcsize) {
    asm volatile("cp.async.cg.shared.global [%0], [%1], 16, %2;"
                 :: "r"(dst), "l"(src), "r"(srcsize) : "memory");
}
__device__ __forceinline__ void cp_commit() {
    asm volatile("cp.async.commit_group;" ::: "memory");
}
template<int Ngroups>
__device__ __forceinline__ void cp_wait() {
    asm volatile("cp.async.wait_group %0;" :: "n"(Ngroups) : "memory");
}
__device__ __forceinline__ void mma16816(float* c, const uint32_t* a, const uint32_t* b) {
    asm volatile("mma.sync.aligned.m16n8k16.row.col.f32.bf16.bf16.f32 "
                 "{%0,%1,%2,%3}, {%4,%5,%6,%7}, {%8,%9}, {%0,%1,%2,%3};"
                 : "+f"(c[0]), "+f"(c[1]), "+f"(c[2]), "+f"(c[3])
                 : "r"(a[0]), "r"(a[1]), "r"(a[2]), "r"(a[3]), "r"(b[0]), "r"(b[1]));
}

template<int EPI>
__global__ __launch_bounds__(256) void k_gemm_mma(
    const __nv_bfloat16* __restrict__ Ahi, const __nv_bfloat16* __restrict__ Alo,
    const __nv_bfloat16* __restrict__ Bhi, const __nv_bfloat16* __restrict__ Blo,
    float* __restrict__ C,
    const float* __restrict__ bias,
    __nv_bfloat16* __restrict__ outHi, __nv_bfloat16* __restrict__ outLo,
    int M, int K, int Nc)
{
    extern __shared__ __align__(16) char smem[];
    const uint32_t sbase = smem_u32(smem);

    int tid = threadIdx.x;
    int wid = tid >> 5;
    int lane = tid & 31;
    int wm = wid & 3;
    int wn = wid >> 2;
    int g = lane >> 2;
    int q = lane & 3;
    int m0 = blockIdx.y * 128;
    int n0 = blockIdx.x * 128;

    float acc[2][8][4];
    #pragma unroll
    for (int mi = 0; mi < 2; mi++)
        #pragma unroll
        for (int ni = 0; ni < 8; ni++)
            #pragma unroll
            for (int r = 0; r < 4; r++) acc[mi][ni][r] = 0.f;

    int nchunks = K >> 5;

    auto load_chunk = [&](int c, int b) {
        uint32_t buf = sbase + b * BUF_BYTES;
        int kc = c * 32;
        #pragma unroll
        for (int i = 0; i < 2; i++) {
            int s   = tid + i * 256;
            int row = s >> 2;
            int cs  = s & 3;
            uint32_t soff = row * (GSTRIDE * 2) + cs * 16;
            int am = m0 + row;
            int ok = (am < M) ? 16 : 0;
            size_t aoff = (size_t)(ok ? am : 0) * K + kc + cs * 8;
            cp16(buf + 0 * TILE_BYTES + soff, Ahi + aoff, ok);
            cp16(buf + 1 * TILE_BYTES + soff, Alo + aoff, ok);
            size_t boff = (size_t)(n0 + row) * K + kc + cs * 8;
            cp16(buf + 2 * TILE_BYTES + soff, Bhi + boff, 16);
            cp16(buf + 3 * TILE_BYTES + soff, Blo + boff, 16);
        }
        cp_commit();
    };

    load_chunk(0, 0);

    for (int c = 0; c < nchunks; c++) {
        if (c + 1 < nchunks) {
            load_chunk(c + 1, (c + 1) & 1);
            cp_wait<1>();
        } else {
            cp_wait<0>();
        }
        __syncthreads();

        uint32_t buf = sbase + (c & 1) * BUF_BYTES;
        uint32_t aHi = buf + 0 * TILE_BYTES;
        uint32_t aLo = buf + 1 * TILE_BYTES;
        uint32_t bHi = buf + 2 * TILE_BYTES;
        uint32_t bLo = buf + 3 * TILE_BYTES;

        #pragma unroll
        for (int ks = 0; ks < 2; ks++) {
            int kb = ks * 32;
            uint32_t ah[2][4], al[2][4];
            #pragma unroll
            for (int mi = 0; mi < 2; mi++) {
                uint32_t a0 = aHi + (wm * 32 + mi * 16 + g) * 80 + kb + q * 4;
                ah[mi][0] = *(const uint32_t*)__cvta_shared_to_generic(a0);
                ah[mi][1] = *(const uint32_t*)__cvta_shared_to_generic(a0 + 640);
                ah[mi][2] = *(const uint32_t*)__cvta_shared_to_generic(a0 + 16);
                ah[mi][3] = *(const uint32_t*)__cvta_shared_to_generic(a0 + 656);
                uint32_t a1 = aLo + (wm * 32 + mi * 16 + g) * 80 + kb + q * 4;
                al[mi][0] = *(const uint32_t*)__cvta_shared_to_generic(a1);
                al[mi][1] = *(const uint32_t*)__cvta_shared_to_generic(a1 + 640);
                al[mi][2] = *(const uint32_t*)__cvta_shared_to_generic(a1 + 16);
                al[mi][3] = *(const uint32_t*)__cvta_shared_to_generic(a1 + 656);
            }
            #pragma unroll
            for (int ni = 0; ni < 8; ni++) {
                uint32_t bh[2], bl[2];
                uint32_t b0 = bHi + (wn * 64 + ni * 8 + g) * 80 + kb + q * 4;
                bh[0] = *(const uint32_t*)__cvta_shared_to_generic(b0);
                bh[1] = *(const uint32_t*)__cvta_shared_to_generic(b0 + 16);
                uint32_t b1 = bLo + (wn * 64 + ni * 8 + g) * 80 + kb + q * 4;
                bl[0] = *(const uint32_t*)__cvta_shared_to_generic(b1);
                bl[1] = *(const uint32_t*)__cvta_shared_to_generic(b1 + 16);
                #pragma unroll
                for (int mi = 0; mi < 2; mi++) {
                    mma16816(acc[mi][ni], ah[mi], bh);
                    mma16816(acc[mi][ni], ah[mi], bl);
                    mma16816(acc[mi][ni], al[mi], bh);
                }
            }
        }
        __syncthreads();
    }

    // ---- epilogue ----
    #pragma unroll
    for (int mi = 0; mi < 2; mi++) {
        int r0 = m0 + wm * 32 + mi * 16 + g;
        int r1 = r0 + 8;
        #pragma unroll
        for (int ni = 0; ni < 8; ni++) {
            int colg = n0 + wn * 64 + ni * 8 + q * 2;
            if (EPI == 0) {
                if (r0 < M)
                    *reinterpret_cast<float2*>(&C[(size_t)r0 * Nc + colg]) =
                        make_float2(acc[mi][ni][0], acc[mi][ni][1]);
                if (r1 < M)
                    *reinterpret_cast<float2*>(&C[(size_t)r1 * Nc + colg]) =
                        make_float2(acc[mi][ni][2], acc[mi][ni][3]);
            } else {
                float2 bb = *reinterpret_cast<const float2*>(&bias[colg]);
                if (r0 < M) {
                    float v0 = fmaxf(acc[mi][ni][0] + bb.x, 0.f);
                    float v1 = fmaxf(acc[mi][ni][1] + bb.y, 0.f);
                    __nv_bfloat162 h, l;
                    split2(v0, v1, h, l);
                    *reinterpret_cast<__nv_bfloat162*>(&outHi[(size_t)r0 * Nc + colg]) = h;
                    *reinterpret_cast<__nv_bfloat162*>(&outLo[(size_t)r0 * Nc + colg]) = l;
                }
                if (r1 < M) {
                    float v0 = fmaxf(acc[mi][ni][2] + bb.x, 0.f);
                    float v1 = fmaxf(acc[mi][ni][3] + bb.y, 0.f);
                    __nv_bfloat162 h, l;
                    split2(v0, v1, h, l);
                    *reinterpret_cast<__nv_bfloat162*>(&outHi[(size_t)r1 * Nc + colg]) = h;
                    *reinterpret_cast<__nv_bfloat162*>(&outLo[(size_t)r1 * Nc + colg]) = l;
                }
            }
        }
    }
}

// ---------------- aggregation: CSR gather, one warp per destination ----------------
// out = [bias +] dinv[n]^2*hw[n,:] + sum coef*hw[src,:]
// RELU: apply relu.  SPLIT: emit bf16 hi/lo, else fp32.

template<int D, bool RELU, bool SPLIT>
__global__ __launch_bounds__(256) void k_gather(const float* __restrict__ hw,
                                                const float* __restrict__ bias,
                                                const float* __restrict__ dinv,
                                                const int* __restrict__ rowptr,
                                                const int2* __restrict__ edges,
                                                float* __restrict__ out,
                                                __nv_bfloat16* __restrict__ outHi,
                                                __nv_bfloat16* __restrict__ outLo,
                                                int N)
{
    constexpr int C = D / 128;
    int n    = (blockIdx.x * blockDim.x + threadIdx.x) >> 5;
    int lane = threadIdx.x & 31;
    if (n >= N) return;

    float di = dinv[n];
    float w  = di * di;

    float4 acc[C];
    #pragma unroll
    for (int c = 0; c < C; c++) {
        int f = (lane + 32 * c) * 4;
        float4 v  = *reinterpret_cast<const float4*>(&hw[(size_t)n * D + f]);
        float4 bb = bias ? *reinterpret_cast<const float4*>(&bias[f])
                         : make_float4(0.f, 0.f, 0.f, 0.f);
        acc[c].x = fmaf(v.x, w, bb.x);
        acc[c].y = fmaf(v.y, w, bb.y);
        acc[c].z = fmaf(v.z, w, bb.z);
        acc[c].w = fmaf(v.w, w, bb.w);
    }

    int e   = rowptr[n];
    int end = rowptr[n + 1];

    for (; e + 1 < end; e += 2) {
        int2 e0 = __ldg(&edges[e]);
        int2 e1 = __ldg(&edges[e + 1]);
        float c0 = __int_as_float(e0.y);
        float c1 = __int_as_float(e1.y);
        const float* s0 = hw + (size_t)e0.x * D;
        const float* s1 = hw + (size_t)e1.x * D;
        #pragma unroll
        for (int c = 0; c < C; c++) {
            int f = (lane + 32 * c) * 4;
            float4 v0 = *reinterpret_cast<const float4*>(&s0[f]);
            float4 v1 = *reinterpret_cast<const float4*>(&s1[f]);
            acc[c].x = fmaf(v0.x, c0, acc[c].x); acc[c].y = fmaf(v0.y, c0, acc[c].y);
            acc[c].z = fmaf(v0.z, c0, acc[c].z); acc[c].w = fmaf(v0.w, c0, acc[c].w);
            acc[c].x = fmaf(v1.x, c1, acc[c].x); acc[c].y = fmaf(v1.y, c1, acc[c].y);
            acc[c].z = fmaf(v1.z, c1, acc[c].z); acc[c].w = fmaf(v1.w, c1, acc[c].w);
        }
    }
    if (e < end) {
        int2 e0 = __ldg(&edges[e]);
        float c0 = __int_as_float(e0.y);
        const float* s0 = hw + (size_t)e0.x * D;
        #pragma unroll
        for (int c = 0; c < C; c++) {
            int f = (lane + 32 * c) * 4;
            float4 v0 = *reinterpret_cast<const float4*>(&s0[f]);
            acc[c].x = fmaf(v0.x, c0, acc[c].x); acc[c].y = fmaf(v0.y, c0, acc[c].y);
            acc[c].z = fmaf(v0.z, c0, acc[c].z); acc[c].w = fmaf(v0.w, c0, acc[c].w);
        }
    }

    #pragma unroll
    for (int c = 0; c < C; c++) {
        int f = (lane + 32 * c) * 4;
        float4 r = acc[c];
        if (RELU) {
            r.x = fmaxf(r.x, 0.f); r.y = fmaxf(r.y, 0.f);
            r.z = fmaxf(r.z, 0.f); r.w = fmaxf(r.w, 0.f);
        }
        if (SPLIT) {
            __nv_bfloat162 h0, l0, h1, l1;
            split2(r.x, r.y, h0, l0);
            split2(r.z, r.w, h1, l1);
            *reinterpret_cast<__nv_bfloat162*>(&outHi[(size_t)n * D + f])     = h0;
            *reinterpret_cast<__nv_bfloat162*>(&outHi[(size_t)n * D + f + 2]) = h1;
            *reinterpret_cast<__nv_bfloat162*>(&outLo[(size_t)n * D + f])     = l0;
            *reinterpret_cast<__nv_bfloat162*>(&outLo[(size_t)n * D + f + 2]) = l1;
        } else {
            *reinterpret_cast<float4*>(&out[(size_t)n * D + f]) = r;
        }
    }
}

// ---------------- launch ----------------

extern "C" void kernel_launch(void* const* d_in, const int* in_sizes, int n_in,
                              void* d_out, int out_size)
{
    const float* x  = (const float*)d_in[0];
    const int*   ei = (const int*)  d_in[1];
    const float* W0 = (const float*)d_in[4];
    const float* b0 = (const float*)d_in[5];
    const float* W1 = (const float*)d_in[6];
    const float* b1 = (const float*)d_in[7];
    const float* W2 = (const float*)d_in[8];
    const float* b2 = (const float*)d_in[9];

    int N = in_sizes[0] / 128;
    int E = in_sizes[1] / 2;
    const int* rowp = ei;
    const int* colp = ei + E;

    float *bufF, *dinv;
    __nv_bfloat16 *bAHi, *bALo, *bBHi, *bBLo, *wtHi, *wtLo;
    int *cnt, *rowptr, *cursor, *blockSums, *blockOff;
    int2 *edges;
    cudaGetSymbolAddress((void**)&bufF,      g_bufF);
    cudaGetSymbolAddress((void**)&bAHi,      g_bAHi);
    cudaGetSymbolAddress((void**)&bALo,      g_bALo);
    cudaGetSymbolAddress((void**)&bBHi,      g_bBHi);
    cudaGetSymbolAddress((void**)&bBLo,      g_bBLo);
    cudaGetSymbolAddress((void**)&wtHi,      g_wtHi);
    cudaGetSymbolAddress((void**)&wtLo,      g_wtLo);
    cudaGetSymbolAddress((void**)&dinv,      g_dinv);
    cudaGetSymbolAddress((void**)&cnt,       g_cnt);
    cudaGetSymbolAddress((void**)&rowptr,    g_rowptr);
    cudaGetSymbolAddress((void**)&cursor,    g_cursor);
    cudaGetSymbolAddress((void**)&blockSums, g_blockSums);
    cudaGetSymbolAddress((void**)&blockOff,  g_blockOff);
    cudaGetSymbolAddress((void**)&edges,     g_edges);

    float* outp = (float*)d_out;

    static bool attrSet = false;
    if (!attrSet) {
        cudaFuncSetAttribute(k_gemm_mma<0>, cudaFuncAttributeMaxDynamicSharedMemorySize,
                             SMEM_TOTAL_G);
        cudaFuncSetAttribute(k_gemm_mma<1>, cudaFuncAttributeMaxDynamicSharedMemorySize,
                             SMEM_TOTAL_G);
        attrSet = true;
    }

    int nb = (N + SCAN_ITEMS - 1) / SCAN_ITEMS;

    // CSR build + norm
    k_zero_cnt<<<(N + 255) / 256, 256>>>(cnt, N);
    k_hist    <<<(E + 255) / 256, 256>>>(colp, cnt, E);
    k_dinv    <<<(N + 255) / 256, 256>>>(cnt, dinv, N);
    k_scan1   <<<nb, 256>>>(cnt, rowptr, blockSums, N);
    k_scan2   <<<1, 64>>>(blockSums, blockOff, nb);
    k_scan3   <<<(N + 255) / 256, 256>>>(rowptr, cursor, blockOff, N, E);
    k_scatter <<<(E + 255) / 256, 256>>>(rowp, colp, dinv, cursor, edges, E);

    // weight splits (transposed)
    k_split_wt<<<(128 * 256 + 255) / 256, 256>>>(W0, wtHi + 0 * 65536, wtLo + 0 * 65536, 128, 256);
    k_split_wt<<<(256 * 256 + 255) / 256, 256>>>(W1, wtHi + 1 * 65536, wtLo + 1 * 65536, 256, 256);
    k_split_wt<<<(256 * 128 + 255) / 256, 256>>>(W2, wtHi + 2 * 65536, wtLo + 2 * 65536, 256, 128);

    int mt = (N + 127) / 128;
    int gatherBlocks = (N * 32 + 255) / 256;

    // L0 (aggregate-first): xa = Â x (D=128), split -> bA
    k_gather<128, false, true><<<gatherBlocks, 256>>>(x, nullptr, dinv, rowptr, edges,
                                                      nullptr, bAHi, bALo, N);
    // GEMM0: h1 = relu(xa@W0 + b0), split in epilogue -> bB
    k_gemm_mma<1><<<dim3(2, mt), 256, SMEM_TOTAL_G>>>(bAHi, bALo,
                                                      wtHi + 0 * 65536, wtLo + 0 * 65536,
                                                      nullptr, b0, bBHi, bBLo, N, 128, 256);
    // L1 (aggregate-after): bufF = h1@W1; h2 = relu(Â bufF + b1), split -> bA
    k_gemm_mma<0><<<dim3(2, mt), 256, SMEM_TOTAL_G>>>(bBHi, bBLo,
                                                      wtHi + 1 * 65536, wtLo + 1 * 65536,
                                                      bufF, nullptr, nullptr, nullptr, N, 256, 256);
    k_gather<256, true, true><<<gatherBlocks, 256>>>(bufF, b1, dinv, rowptr, edges,
                                                     nullptr, bAHi, bALo, N);
    // L2 (aggregate-after): bufF = h2@W2 (D=128); out = Â bufF + b2
    k_gemm_mma<0><<<dim3(1, mt), 256, SMEM_TOTAL_G>>>(bAHi, bALo,
                                                      wtHi + 2 * 65536, wtLo + 2 * 65536,
                                                      bufF, nullptr, nullptr, nullptr, N, 256, 128);
    k_gather<128, false, false><<<gatherBlocks, 256>>>(bufF, b2, dinv, rowptr, edges,
                                                       outp, nullptr, nullptr, N);
}

// round 7
// speedup vs baseline: 3.7699x; 1.0229x over previous
#include <cuda_runtime.h>
#include <cuda_bf16.h>
#include <math.h>
#include <stdint.h>

#define MAXN 100000
#define MAXE 1600000
#define DHID 256
#define SCAN_ITEMS 2048   // 256 threads x 8 items

// ---------------- scratch (__device__ globals; allocation-free rule) ----------------
__device__ float          g_bufF[MAXN * DHID];       // fp32 GEMM output
__device__ __nv_bfloat16  g_bAHi[MAXN * DHID];       // bf16 split buffers (ping)
__device__ __nv_bfloat16  g_bALo[MAXN * DHID];
__device__ __nv_bfloat16  g_bBHi[MAXN * DHID];       // bf16 split buffers (pong)
__device__ __nv_bfloat16  g_bBLo[MAXN * DHID];
__device__ __nv_bfloat16  g_wtHi[3][65536];          // transposed weights, split
__device__ __nv_bfloat16  g_wtLo[3][65536];
__device__ float g_dinv[MAXN];
__device__ int   g_cnt   [MAXN];
__device__ int   g_rowptr[MAXN + 1];
__device__ int   g_cursor[MAXN];
__device__ int   g_blockSums[64];
__device__ int2  g_edges[MAXE];

// ---------------- CSR build ----------------

__global__ void k_zero_cnt(int* cnt, int N) {
    int i = blockIdx.x * blockDim.x + threadIdx.x;
    if (i < N) cnt[i] = 0;
}
__global__ void k_hist(const int* __restrict__ col, int* cnt, int E) {
    int i = blockIdx.x * blockDim.x + threadIdx.x;
    if (i < E) atomicAdd(&cnt[col[i]], 1);
}

// scan1 + dinv fused: block-level exclusive scan over cnt, plus dinv = rsqrt(cnt+1)
__global__ __launch_bounds__(256) void k_scan1d(const int* __restrict__ cnt,
                                                int* rowptr, int* blockSums,
                                                float* __restrict__ dinv, int N) {
    __shared__ int sh[256];
    int base = blockIdx.x * SCAN_ITEMS;
    int vals[8];
    int sum = 0;
    #pragma unroll
    for (int j = 0; j < 8; j++) {
        int idx = base + threadIdx.x * 8 + j;
        int v = (idx < N) ? cnt[idx] : 0;
        if (idx < N) dinv[idx] = rsqrtf((float)(v + 1));
        vals[j] = sum;
        sum += v;
    }
    sh[threadIdx.x] = sum;
    __syncthreads();
    #pragma unroll
    for (int off = 1; off < 256; off <<= 1) {
        int t = (threadIdx.x >= off) ? sh[threadIdx.x - off] : 0;
        __syncthreads();
        sh[threadIdx.x] += t;
        __syncthreads();
    }
    int thOff = (threadIdx.x > 0) ? sh[threadIdx.x - 1] : 0;
    #pragma unroll
    for (int j = 0; j < 8; j++) {
        int idx = base + threadIdx.x * 8 + j;
        if (idx < N) rowptr[idx] = thOff + vals[j];
    }
    if (threadIdx.x == 255) blockSums[blockIdx.x] = sh[255];
}

// scan2 + scan3 fused: each block re-prefixes the (<=64) block sums in smem
__global__ __launch_bounds__(256) void k_scan3b(int* rowptr, int* cursor,
                                                const int* __restrict__ blockSums,
                                                int nb, int N, int E) {
    __shared__ int off[64];
    if (threadIdx.x < 64) off[threadIdx.x] = (threadIdx.x < nb) ? blockSums[threadIdx.x] : 0;
    __syncthreads();
    if (threadIdx.x == 0) {
        int s = 0;
        #pragma unroll
        for (int i = 0; i < 64; i++) { int t = off[i]; off[i] = s; s += t; }
    }
    __syncthreads();
    int i = blockIdx.x * blockDim.x + threadIdx.x;
    if (i < N) {
        int v = rowptr[i] + off[i / SCAN_ITEMS];
        rowptr[i] = v;
        cursor[i] = v;
    }
    if (i == 0) rowptr[N] = E;
}

__global__ void k_scatter(const int* __restrict__ row, const int* __restrict__ col,
                          const float* __restrict__ dinv, int* cursor,
                          int2* edges, int E) {
    int i = blockIdx.x * blockDim.x + threadIdx.x;
    if (i >= E) return;
    int r = row[i], c = col[i];
    int p = atomicAdd(&cursor[c], 1);
    float coef = dinv[r] * dinv[c];
    edges[p] = make_int2(r, __float_as_int(coef));
}

// ---------------- fp32 -> bf16 hi/lo split helpers ----------------

__device__ __forceinline__ void split2(float a, float b,
                                       __nv_bfloat162& hi, __nv_bfloat162& lo) {
    __nv_bfloat16 ha = __float2bfloat16(a);
    __nv_bfloat16 hb = __float2bfloat16(b);
    __nv_bfloat16 la = __float2bfloat16(a - __bfloat162float(ha));
    __nv_bfloat16 lb = __float2bfloat16(b - __bfloat162float(hb));
    hi = __halves2bfloat162(ha, hb);
    lo = __halves2bfloat162(la, lb);
}

// transpose + split W [K,Nc] -> WT hi/lo [Nc,K]
__global__ void k_split_wt(const float* __restrict__ W,
                           __nv_bfloat16* __restrict__ oh,
                           __nv_bfloat16* __restrict__ ol, int K, int Nc) {
    int t = blockIdx.x * blockDim.x + threadIdx.x;
    if (t >= K * Nc) return;
    int n = t / K, k = t % K;
    float a = W[k * Nc + n];
    __nv_bfloat16 h = __float2bfloat16(a);
    __nv_bfloat16 l = __float2bfloat16(a - __bfloat162float(h));
    oh[t] = h;
    ol[t] = l;
}

// ---------------- tensor-core GEMM via mma.sync (bf16, 3-term split) ----------------
// C[M,Nc] = (Ahi+Alo)[M,K] @ (WThi+WTlo)^T, fp32 accum.
// EPI=0: write fp32 C.  EPI=1: relu(C + bias) -> bf16 hi/lo split outputs.
// CTA: 128x128 tile, BK=32, 256 threads = 8 warps (4m x 2n), warp tile 32x64.

#define GSTRIDE 40                       // smem row stride in bf16 (80 B)
#define TILE_BYTES (128 * GSTRIDE * 2)   // 10240 B per tile
#define BUF_BYTES  (4 * TILE_BYTES)
#define SMEM_TOTAL_G (2 * BUF_BYTES)     // 81920 B

__device__ __forceinline__ uint32_t smem_u32(const void* p) {
    uint32_t a;
    asm("{ .reg .u64 t; cvta.to.shared.u64 t, %1; cvt.u32.u64 %0, t; }" : "=r"(a) : "l"(p));
    return a;
}
__device__ __forceinline__ void cp16(uint32_t dst, const void* src, int srcsize) {
    asm volatile("cp.async.cg.shared.global [%0], [%1], 16, %2;"
                 :: "r"(dst), "l"(src), "r"(srcsize) : "memory");
}
__device__ __forceinline__ void cp_commit() {
    asm volatile("cp.async.commit_group;" ::: "memory");
}
template<int Ngroups>
__device__ __forceinline__ void cp_wait() {
    asm volatile("cp.async.wait_group %0;" :: "n"(Ngroups) : "memory");
}
__device__ __forceinline__ void mma16816(float* c, const uint32_t* a, const uint32_t* b) {
    asm volatile("mma.sync.aligned.m16n8k16.row.col.f32.bf16.bf16.f32 "
                 "{%0,%1,%2,%3}, {%4,%5,%6,%7}, {%8,%9}, {%0,%1,%2,%3};"
                 : "+f"(c[0]), "+f"(c[1]), "+f"(c[2]), "+f"(c[3])
                 : "r"(a[0]), "r"(a[1]), "r"(a[2]), "r"(a[3]), "r"(b[0]), "r"(b[1]));
}

template<int EPI>
__global__ __launch_bounds__(256) void k_gemm_mma(
    const __nv_bfloat16* __restrict__ Ahi, const __nv_bfloat16* __restrict__ Alo,
    const __nv_bfloat16* __restrict__ Bhi, const __nv_bfloat16* __restrict__ Blo,
    float* __restrict__ C,
    const float* __restrict__ bias,
    __nv_bfloat16* __restrict__ outHi, __nv_bfloat16* __restrict__ outLo,
    int M, int K, int Nc)
{
    extern __shared__ __align__(16) char smem[];
    const uint32_t sbase = smem_u32(smem);

    int tid = threadIdx.x;
    int wid = tid >> 5;
    int lane = tid & 31;
    int wm = wid & 3;
    int wn = wid >> 2;
    int g = lane >> 2;
    int q = lane & 3;
    int m0 = blockIdx.y * 128;
    int n0 = blockIdx.x * 128;

    float acc[2][8][4];
    #pragma unroll
    for (int mi = 0; mi < 2; mi++)
        #pragma unroll
        for (int ni = 0; ni < 8; ni++)
            #pragma unroll
            for (int r = 0; r < 4; r++) acc[mi][ni][r] = 0.f;

    int nchunks = K >> 5;

    auto load_chunk = [&](int c, int b) {
        uint32_t buf = sbase + b * BUF_BYTES;
        int kc = c * 32;
        #pragma unroll
        for (int i = 0; i < 2; i++) {
            int s   = tid + i * 256;
            int row = s >> 2;
            int cs  = s & 3;
            uint32_t soff = row * (GSTRIDE * 2) + cs * 16;
            int am = m0 + row;
            int ok = (am < M) ? 16 : 0;
            size_t aoff = (size_t)(ok ? am : 0) * K + kc + cs * 8;
            cp16(buf + 0 * TILE_BYTES + soff, Ahi + aoff, ok);
            cp16(buf + 1 * TILE_BYTES + soff, Alo + aoff, ok);
            size_t boff = (size_t)(n0 + row) * K + kc + cs * 8;
            cp16(buf + 2 * TILE_BYTES + soff, Bhi + boff, 16);
            cp16(buf + 3 * TILE_BYTES + soff, Blo + boff, 16);
        }
        cp_commit();
    };

    load_chunk(0, 0);

    for (int c = 0; c < nchunks; c++) {
        if (c + 1 < nchunks) {
            load_chunk(c + 1, (c + 1) & 1);
            cp_wait<1>();
        } else {
            cp_wait<0>();
        }
        __syncthreads();

        uint32_t buf = sbase + (c & 1) * BUF_BYTES;
        uint32_t aHi = buf + 0 * TILE_BYTES;
        uint32_t aLo = buf + 1 * TILE_BYTES;
        uint32_t bHi = buf + 2 * TILE_BYTES;
        uint32_t bLo = buf + 3 * TILE_BYTES;

        #pragma unroll
        for (int ks = 0; ks < 2; ks++) {
            int kb = ks * 32;
            uint32_t ah[2][4], al[2][4];
            #pragma unroll
            for (int mi = 0; mi < 2; mi++) {
                uint32_t a0 = aHi + (wm * 32 + mi * 16 + g) * 80 + kb + q * 4;
                ah[mi][0] = *(const uint32_t*)__cvta_shared_to_generic(a0);
                ah[mi][1] = *(const uint32_t*)__cvta_shared_to_generic(a0 + 640);
                ah[mi][2] = *(const uint32_t*)__cvta_shared_to_generic(a0 + 16);
                ah[mi][3] = *(const uint32_t*)__cvta_shared_to_generic(a0 + 656);
                uint32_t a1 = aLo + (wm * 32 + mi * 16 + g) * 80 + kb + q * 4;
                al[mi][0] = *(const uint32_t*)__cvta_shared_to_generic(a1);
                al[mi][1] = *(const uint32_t*)__cvta_shared_to_generic(a1 + 640);
                al[mi][2] = *(const uint32_t*)__cvta_shared_to_generic(a1 + 16);
                al[mi][3] = *(const uint32_t*)__cvta_shared_to_generic(a1 + 656);
            }
            #pragma unroll
            for (int ni = 0; ni < 8; ni++) {
                uint32_t bh[2], bl[2];
                uint32_t b0 = bHi + (wn * 64 + ni * 8 + g) * 80 + kb + q * 4;
                bh[0] = *(const uint32_t*)__cvta_shared_to_generic(b0);
                bh[1] = *(const uint32_t*)__cvta_shared_to_generic(b0 + 16);
                uint32_t b1 = bLo + (wn * 64 + ni * 8 + g) * 80 + kb + q * 4;
                bl[0] = *(const uint32_t*)__cvta_shared_to_generic(b1);
                bl[1] = *(const uint32_t*)__cvta_shared_to_generic(b1 + 16);
                #pragma unroll
                for (int mi = 0; mi < 2; mi++) {
                    mma16816(acc[mi][ni], ah[mi], bh);
                    mma16816(acc[mi][ni], ah[mi], bl);
                    mma16816(acc[mi][ni], al[mi], bh);
                }
            }
        }
        __syncthreads();
    }

    // ---- epilogue ----
    #pragma unroll
    for (int mi = 0; mi < 2; mi++) {
        int r0 = m0 + wm * 32 + mi * 16 + g;
        int r1 = r0 + 8;
        #pragma unroll
        for (int ni = 0; ni < 8; ni++) {
            int colg = n0 + wn * 64 + ni * 8 + q * 2;
            if (EPI == 0) {
                if (r0 < M)
                    *reinterpret_cast<float2*>(&C[(size_t)r0 * Nc + colg]) =
                        make_float2(acc[mi][ni][0], acc[mi][ni][1]);
                if (r1 < M)
                    *reinterpret_cast<float2*>(&C[(size_t)r1 * Nc + colg]) =
                        make_float2(acc[mi][ni][2], acc[mi][ni][3]);
            } else {
                float2 bb = *reinterpret_cast<const float2*>(&bias[colg]);
                if (r0 < M) {
                    float v0 = fmaxf(acc[mi][ni][0] + bb.x, 0.f);
                    float v1 = fmaxf(acc[mi][ni][1] + bb.y, 0.f);
                    __nv_bfloat162 h, l;
                    split2(v0, v1, h, l);
                    *reinterpret_cast<__nv_bfloat162*>(&outHi[(size_t)r0 * Nc + colg]) = h;
                    *reinterpret_cast<__nv_bfloat162*>(&outLo[(size_t)r0 * Nc + colg]) = l;
                }
                if (r1 < M) {
                    float v0 = fmaxf(acc[mi][ni][2] + bb.x, 0.f);
                    float v1 = fmaxf(acc[mi][ni][3] + bb.y, 0.f);
                    __nv_bfloat162 h, l;
                    split2(v0, v1, h, l);
                    *reinterpret_cast<__nv_bfloat162*>(&outHi[(size_t)r1 * Nc + colg]) = h;
                    *reinterpret_cast<__nv_bfloat162*>(&outLo[(size_t)r1 * Nc + colg]) = l;
                }
            }
        }
    }
}

// ---------------- aggregation: CSR gather, one warp per destination ----------------
// out = [bias +] dinv[n]^2*hw[n,:] + sum coef*hw[src,:]
// RELU: apply relu.  SPLIT: emit bf16 hi/lo, else fp32.

template<int D, bool RELU, bool SPLIT>
__global__ __launch_bounds__(256) void k_gather(const float* __restrict__ hw,
                                                const float* __restrict__ bias,
                                                const float* __restrict__ dinv,
                                                const int* __restrict__ rowptr,
                                                const int2* __restrict__ edges,
                                                float* __restrict__ out,
                                                __nv_bfloat16* __restrict__ outHi,
                                                __nv_bfloat16* __restrict__ outLo,
                                                int N)
{
    constexpr int C = D / 128;
    int n    = (blockIdx.x * blockDim.x + threadIdx.x) >> 5;
    int lane = threadIdx.x & 31;
    if (n >= N) return;

    float di = dinv[n];
    float w  = di * di;

    float4 acc[C];
    #pragma unroll
    for (int c = 0; c < C; c++) {
        int f = (lane + 32 * c) * 4;
        float4 v  = *reinterpret_cast<const float4*>(&hw[(size_t)n * D + f]);
        float4 bb = bias ? *reinterpret_cast<const float4*>(&bias[f])
                         : make_float4(0.f, 0.f, 0.f, 0.f);
        acc[c].x = fmaf(v.x, w, bb.x);
        acc[c].y = fmaf(v.y, w, bb.y);
        acc[c].z = fmaf(v.z, w, bb.z);
        acc[c].w = fmaf(v.w, w, bb.w);
    }

    int e   = rowptr[n];
    int end = rowptr[n + 1];

    // 4-edge unroll for deeper MLP against L2 latency
    for (; e + 3 < end; e += 4) {
        int2 e0 = __ldg(&edges[e]);
        int2 e1 = __ldg(&edges[e + 1]);
        int2 e2 = __ldg(&edges[e + 2]);
        int2 e3 = __ldg(&edges[e + 3]);
        float c0 = __int_as_float(e0.y), c1 = __int_as_float(e1.y);
        float c2 = __int_as_float(e2.y), c3 = __int_as_float(e3.y);
        const float* s0 = hw + (size_t)e0.x * D;
        const float* s1 = hw + (size_t)e1.x * D;
        const float* s2 = hw + (size_t)e2.x * D;
        const float* s3 = hw + (size_t)e3.x * D;
        #pragma unroll
        for (int c = 0; c < C; c++) {
            int f = (lane + 32 * c) * 4;
            float4 v0 = *reinterpret_cast<const float4*>(&s0[f]);
            float4 v1 = *reinterpret_cast<const float4*>(&s1[f]);
            float4 v2 = *reinterpret_cast<const float4*>(&s2[f]);
            float4 v3 = *reinterpret_cast<const float4*>(&s3[f]);
            acc[c].x = fmaf(v0.x, c0, acc[c].x); acc[c].y = fmaf(v0.y, c0, acc[c].y);
            acc[c].z = fmaf(v0.z, c0, acc[c].z); acc[c].w = fmaf(v0.w, c0, acc[c].w);
            acc[c].x = fmaf(v1.x, c1, acc[c].x); acc[c].y = fmaf(v1.y, c1, acc[c].y);
            acc[c].z = fmaf(v1.z, c1, acc[c].z); acc[c].w = fmaf(v1.w, c1, acc[c].w);
            acc[c].x = fmaf(v2.x, c2, acc[c].x); acc[c].y = fmaf(v2.y, c2, acc[c].y);
            acc[c].z = fmaf(v2.z, c2, acc[c].z); acc[c].w = fmaf(v2.w, c2, acc[c].w);
            acc[c].x = fmaf(v3.x, c3, acc[c].x); acc[c].y = fmaf(v3.y, c3, acc[c].y);
            acc[c].z = fmaf(v3.z, c3, acc[c].z); acc[c].w = fmaf(v3.w, c3, acc[c].w);
        }
    }
    for (; e < end; e++) {
        int2 e0 = __ldg(&edges[e]);
        float c0 = __int_as_float(e0.y);
        const float* s0 = hw + (size_t)e0.x * D;
        #pragma unroll
        for (int c = 0; c < C; c++) {
            int f = (lane + 32 * c) * 4;
            float4 v0 = *reinterpret_cast<const float4*>(&s0[f]);
            acc[c].x = fmaf(v0.x, c0, acc[c].x); acc[c].y = fmaf(v0.y, c0, acc[c].y);
            acc[c].z = fmaf(v0.z, c0, acc[c].z); acc[c].w = fmaf(v0.w, c0, acc[c].w);
        }
    }

    #pragma unroll
    for (int c = 0; c < C; c++) {
        int f = (lane + 32 * c) * 4;
        float4 r = acc[c];
        if (RELU) {
            r.x = fmaxf(r.x, 0.f); r.y = fmaxf(r.y, 0.f);
            r.z = fmaxf(r.z, 0.f); r.w = fmaxf(r.w, 0.f);
        }
        if (SPLIT) {
            __nv_bfloat162 h0, l0, h1, l1;
            split2(r.x, r.y, h0, l0);
            split2(r.z, r.w, h1, l1);
            *reinterpret_cast<__nv_bfloat162*>(&outHi[(size_t)n * D + f])     = h0;
            *reinterpret_cast<__nv_bfloat162*>(&outHi[(size_t)n * D + f + 2]) = h1;
            *reinterpret_cast<__nv_bfloat162*>(&outLo[(size_t)n * D + f])     = l0;
            *reinterpret_cast<__nv_bfloat162*>(&outLo[(size_t)n * D + f + 2]) = l1;
        } else {
            *reinterpret_cast<float4*>(&out[(size_t)n * D + f]) = r;
        }
    }
}

// ---------------- launch ----------------

extern "C" void kernel_launch(void* const* d_in, const int* in_sizes, int n_in,
                              void* d_out, int out_size)
{
    const float* x  = (const float*)d_in[0];
    const int*   ei = (const int*)  d_in[1];
    const float* W0 = (const float*)d_in[4];
    const float* b0 = (const float*)d_in[5];
    const float* W1 = (const float*)d_in[6];
    const float* b1 = (const float*)d_in[7];
    const float* W2 = (const float*)d_in[8];
    const float* b2 = (const float*)d_in[9];

    int N = in_sizes[0] / 128;
    int E = in_sizes[1] / 2;
    const int* rowp = ei;
    const int* colp = ei + E;

    float *bufF, *dinv;
    __nv_bfloat16 *bAHi, *bALo, *bBHi, *bBLo, *wtHi, *wtLo;
    int *cnt, *rowptr, *cursor, *blockSums;
    int2 *edges;
    cudaGetSymbolAddress((void**)&bufF,      g_bufF);
    cudaGetSymbolAddress((void**)&bAHi,      g_bAHi);
    cudaGetSymbolAddress((void**)&bALo,      g_bALo);
    cudaGetSymbolAddress((void**)&bBHi,      g_bBHi);
    cudaGetSymbolAddress((void**)&bBLo,      g_bBLo);
    cudaGetSymbolAddress((void**)&wtHi,      g_wtHi);
    cudaGetSymbolAddress((void**)&wtLo,      g_wtLo);
    cudaGetSymbolAddress((void**)&dinv,      g_dinv);
    cudaGetSymbolAddress((void**)&cnt,       g_cnt);
    cudaGetSymbolAddress((void**)&rowptr,    g_rowptr);
    cudaGetSymbolAddress((void**)&cursor,    g_cursor);
    cudaGetSymbolAddress((void**)&blockSums, g_blockSums);
    cudaGetSymbolAddress((void**)&edges,     g_edges);

    float* outp = (float*)d_out;

    static cudaStream_t s2 = nullptr;
    static cudaEvent_t evFork = nullptr, evJoin = nullptr;
    static bool initDone = false;
    if (!initDone) {
        cudaFuncSetAttribute(k_gemm_mma<0>, cudaFuncAttributeMaxDynamicSharedMemorySize,
                             SMEM_TOTAL_G);
        cudaFuncSetAttribute(k_gemm_mma<1>, cudaFuncAttributeMaxDynamicSharedMemorySize,
                             SMEM_TOTAL_G);
        cudaStreamCreateWithFlags(&s2, cudaStreamNonBlocking);
        cudaEventCreateWithFlags(&evFork, cudaEventDisableTiming);
        cudaEventCreateWithFlags(&evJoin, cudaEventDisableTiming);
        initDone = true;
    }

    int nb = (N + SCAN_ITEMS - 1) / SCAN_ITEMS;

    // ---- fork: weight splits on side stream, concurrent with CSR build + L0 gather
    cudaEventRecord(evFork, 0);
    cudaStreamWaitEvent(s2, evFork, 0);
    k_split_wt<<<(128 * 256 + 255) / 256, 256, 0, s2>>>(W0, wtHi + 0 * 65536, wtLo + 0 * 65536, 128, 256);
    k_split_wt<<<(256 * 256 + 255) / 256, 256, 0, s2>>>(W1, wtHi + 1 * 65536, wtLo + 1 * 65536, 256, 256);
    k_split_wt<<<(256 * 128 + 255) / 256, 256, 0, s2>>>(W2, wtHi + 2 * 65536, wtLo + 2 * 65536, 256, 128);
    cudaEventRecord(evJoin, s2);

    // ---- main stream: CSR build + norm (fused: 5 kernels)
    k_zero_cnt<<<(N + 255) / 256, 256>>>(cnt, N);
    k_hist    <<<(E + 255) / 256, 256>>>(colp, cnt, E);
    k_scan1d  <<<nb, 256>>>(cnt, rowptr, blockSums, dinv, N);
    k_scan3b  <<<(N + 255) / 256, 256>>>(rowptr, cursor, blockSums, nb, N, E);
    k_scatter <<<(E + 255) / 256, 256>>>(rowp, colp, dinv, cursor, edges, E);

    int mt = (N + 127) / 128;
    int gatherBlocks = (N * 32 + 255) / 256;

    // L0 (aggregate-first): xa = Â x (D=128), split -> bA
    k_gather<128, false, true><<<gatherBlocks, 256>>>(x, nullptr, dinv, rowptr, edges,
                                                      nullptr, bAHi, bALo, N);

    // ---- join: GEMMs need the weight splits
    cudaStreamWaitEvent(0, evJoin, 0);

    // GEMM0: h1 = relu(xa@W0 + b0), split in epilogue -> bB
    k_gemm_mma<1><<<dim3(2, mt), 256, SMEM_TOTAL_G>>>(bAHi, bALo,
                                                      wtHi + 0 * 65536, wtLo + 0 * 65536,
                                                      nullptr, b0, bBHi, bBLo, N, 128, 256);
    // L1 (aggregate-after): bufF = h1@W1; h2 = relu(Â bufF + b1), split -> bA
    k_gemm_mma<0><<<dim3(2, mt), 256, SMEM_TOTAL_G>>>(bBHi, bBLo,
                                                      wtHi + 1 * 65536, wtLo + 1 * 65536,
                                                      bufF, nullptr, nullptr, nullptr, N, 256, 256);
    k_gather<256, true, true><<<gatherBlocks, 256>>>(bufF, b1, dinv, rowptr, edges,
                                                     nullptr, bAHi, bALo, N);
    // L2 (aggregate-after): bufF = h2@W2 (D=128); out = Â bufF + b2
    k_gemm_mma<0><<<dim3(1, mt), 256, SMEM_TOTAL_G>>>(bAHi, bALo,
                                                      wtHi + 2 * 65536, wtLo + 2 * 65536,
                                                      bufF, nullptr, nullptr, nullptr, N, 256, 128);
    k_gather<128, false, false><<<gatherBlocks, 256>>>(bufF, b2, dinv, rowptr, edges,
                                                       outp, nullptr, nullptr, N);
}